// round 12
// baseline (speedup 1.0000x reference)
#include <cuda_runtime.h>
#include <cuda_fp16.h>
#include <cstdint>

constexpr int NB = 8, NE = 64, NCIN = 128, NC = 128;

__device__ __forceinline__ float leaky(float v) { return v >= 0.f ? v : 0.1f * v; }

// ---------------- scratch (static device globals) ----------------
__device__ float  d_xf[NB * NC * NE];
__device__ float  d_yf[NB * NC * NE];
__device__ float  d_xs[NB * NE];
__device__ float  d_yo[NB * NE];
__device__ float  d_pltype[20];
__device__ float  d_eltype[10];
__device__ float  d_wx[NCIN];
__device__ float  d_wy[NCIN];
__device__ float  d_g[NB * NE * NE];
__device__ float  d_xlin[NB * NE * NCIN];
__device__ float  d_ylin[NB * NE * NCIN];
__device__ __half d_menh[NB * 4096 * 256];   // path_fea [b][pix][c]
__device__ __half d_hh[NB * 4096 * NC];      // conv1 out [b][pix][c]
__device__ __half d_w1h[NC * 384];
__device__ __half d_w2s[9 * NC * NC];

__device__ __forceinline__ uint32_t smem_to_u32(const void* p) {
    uint32_t a;
    asm("{ .reg .u64 t; cvta.to.shared.u64 t, %1; cvt.u32.u64 %0, t; }" : "=r"(a) : "l"(p));
    return a;
}
#define LDSM_X4(r0, r1, r2, r3, addr) \
    asm volatile("ldmatrix.sync.aligned.m8n8.x4.shared.b16 {%0,%1,%2,%3}, [%4];" \
        : "=r"(r0), "=r"(r1), "=r"(r2), "=r"(r3) : "r"(addr))
#define LDSM_X2(r0, r1, addr) \
    asm volatile("ldmatrix.sync.aligned.m8n8.x2.shared.b16 {%0,%1}, [%2];" \
        : "=r"(r0), "=r"(r1) : "r"(addr))
__device__ __forceinline__ void mma16816(float* c, const uint32_t* a, const uint32_t* b) {
    asm volatile("mma.sync.aligned.m16n8k16.row.col.f32.f16.f16.f32 "
                 "{%0,%1,%2,%3}, {%4,%5,%6,%7}, {%8,%9}, {%0,%1,%2,%3};"
                 : "+f"(c[0]), "+f"(c[1]), "+f"(c[2]), "+f"(c[3])
                 : "r"(a[0]), "r"(a[1]), "r"(a[2]), "r"(a[3]), "r"(b[0]), "r"(b[1]));
}
constexpr int PITCH = 72;
constexpr int TPITCH = 136;

// ---------------- merged init ----------------
__global__ void k_init(const float* __restrict__ w1, const float* __restrict__ w2,
                       const float* __restrict__ path_table, const float* __restrict__ pconv_w,
                       const float* __restrict__ edge_table, const float* __restrict__ econv_w,
                       const float* __restrict__ xc1_w, const float* __restrict__ yc1_w,
                       const float* __restrict__ xc2_w, const float* __restrict__ yc2_w) {
    int blk = blockIdx.x, t = threadIdx.x;
    if (blk < 192) {
        int i = blk * 256 + t;
        d_w1h[i] = __float2half(w1[i]);
    } else if (blk < 768) {
        int i = (blk - 192) * 256 + t;
        int shift = i / 16384, rem = i % 16384;
        int o = rem >> 7, c = rem & 127;
        d_w2s[i] = __float2half(w2[(o * NC + c) * 9 + shift]);
    } else {
        if (t < 20) {
            float s = 0.f;
            #pragma unroll
            for (int d = 0; d < 32; d++) s += path_table[t * 32 + d] * pconv_w[d];
            d_pltype[t] = leaky(s);
        }
        if (t < 10) {
            float s = 0.f;
            #pragma unroll
            for (int d = 0; d < 32; d++) s += edge_table[t * 32 + d] * econv_w[d];
            d_eltype[t] = leaky(s);
        }
        if (t < 128) {
            float ax = 0.f, ay = 0.f;
            #pragma unroll 8
            for (int c = 0; c < NC; c++) {
                ax += xc2_w[c] * xc1_w[c * NCIN + t];
                ay += yc2_w[c] * yc1_w[c * NCIN + t];
            }
            d_wx[t] = ax; d_wy[t] = ay;
        }
    }
}

// ---------------- x_f / y_f via mma.sync ----------------
__global__ __launch_bounds__(256) void k_xfyf(const float* __restrict__ x, const float* __restrict__ y,
                                              const float* __restrict__ xw, const float* __restrict__ yw) {
    __shared__ __align__(16) __half As[128 * PITCH];
    __shared__ __align__(16) __half Bs[64 * PITCH];
    int b = blockIdx.x, z = blockIdx.y;
    const float* w  = z ? yw : xw;
    const float* in = (z ? y : x) + b * NCIN * NE;
    float* outp     = (z ? d_yf : d_xf) + b * NC * NE;
    int tid = threadIdx.x, lane = tid & 31, wp = tid >> 5;
    int wm = wp >> 1, wn = wp & 1;
    uint32_t smA = smem_to_u32(As), smB = smem_to_u32(Bs);
    float acc[2][4][4];
    #pragma unroll
    for (int mi = 0; mi < 2; mi++)
        #pragma unroll
        for (int ni = 0; ni < 4; ni++)
            #pragma unroll
            for (int q = 0; q < 4; q++) acc[mi][ni][q] = 0.f;

    for (int k0 = 0; k0 < 128; k0 += 64) {
        __syncthreads();
        for (int idx = tid; idx < 4096; idx += 256) {
            int c = idx >> 5, i2 = idx & 31;
            float2 f = *(const float2*)(w + c * 128 + k0 + i2 * 2);
            *(__half2*)&As[c * PITCH + i2 * 2] = __floats2half2_rn(f.x, f.y);
        }
        for (int idx = tid; idx < 2048; idx += 256) {
            int i = idx >> 5, m2 = idx & 31;
            float2 f = *(const float2*)(in + (k0 + i) * 64 + m2 * 2);
            Bs[(m2 * 2) * PITCH + i]     = __float2half(f.x);
            Bs[(m2 * 2 + 1) * PITCH + i] = __float2half(f.y);
        }
        __syncthreads();
        #pragma unroll
        for (int ks = 0; ks < 4; ks++) {
            uint32_t a[2][4], bf[4][2];
            #pragma unroll
            for (int mi = 0; mi < 2; mi++) {
                uint32_t ad = smA + ((wm * 32 + mi * 16 + (lane & 15)) * PITCH + ks * 16 + (lane >> 4) * 8) * 2;
                LDSM_X4(a[mi][0], a[mi][1], a[mi][2], a[mi][3], ad);
            }
            #pragma unroll
            for (int ni = 0; ni < 4; ni++) {
                uint32_t ad = smB + ((wn * 32 + ni * 8 + (lane & 7)) * PITCH + ks * 16 + ((lane >> 3) & 1) * 8) * 2;
                LDSM_X2(bf[ni][0], bf[ni][1], ad);
            }
            #pragma unroll
            for (int mi = 0; mi < 2; mi++)
                #pragma unroll
                for (int ni = 0; ni < 4; ni++) mma16816(acc[mi][ni], a[mi], bf[ni]);
        }
    }
    #pragma unroll
    for (int mi = 0; mi < 2; mi++) {
        int c = wm * 32 + mi * 16 + (lane >> 2);
        #pragma unroll
        for (int ni = 0; ni < 4; ni++) {
            int m = wn * 32 + ni * 8 + (lane & 3) * 2;
            *(float2*)(outp + c * 64 + m)       = make_float2(acc[mi][ni][0], acc[mi][ni][1]);
            *(float2*)(outp + (c + 8) * 64 + m) = make_float2(acc[mi][ni][2], acc[mi][ni][3]);
        }
    }
}

// ---------------- x_self / y_other vectors only ----------------
__global__ void k_selfvec(const float* __restrict__ x, const float* __restrict__ y,
                          const float* __restrict__ xc2_b, const float* __restrict__ yc2_b) {
    int b = blockIdx.x, t = threadIdx.x;
    if (t < 64) {
        const float* xb = x + b * NCIN * NE + t;
        float a0 = 0.f, a1 = 0.f;
        #pragma unroll 8
        for (int i = 0; i < NCIN; i += 2) { a0 += d_wx[i] * xb[i * NE]; a1 += d_wx[i + 1] * xb[(i + 1) * NE]; }
        d_xs[b * 64 + t] = a0 + a1 + xc2_b[0];
    } else {
        int m = t - 64;
        const float* yb = y + b * NCIN * NE + m;
        float a0 = 0.f, a1 = 0.f;
        #pragma unroll 8
        for (int i = 0; i < NCIN; i += 2) { a0 += d_wy[i] * yb[i * NE]; a1 += d_wy[i + 1] * yb[(i + 1) * NE]; }
        d_yo[b * 64 + m] = a0 + a1 + yc2_b[0];
    }
}

// ---------------- per-(b,e) path attention: 512 threads, inline L, smem pltype ----------------
__global__ __launch_bounds__(512) void k_attn(const int* __restrict__ path_mat,
                                              const float* __restrict__ p_bias) {
    __shared__ __align__(16) float  loc[64 * 64];
    __shared__ __align__(16) __half Ah[64 * 64];
    __shared__ __align__(16) __half Fh[64 * TPITCH];
    __shared__ float rmax[64], rinv[64], cmax[64], cinv[64];
    __shared__ float sxs[64], syo[64], spl[20];
    int e = blockIdx.x, b = blockIdx.y, t = threadIdx.x;
    int lane = t & 31, w = t >> 5;
    const int*   pm = path_mat + (b * NE + e) * 4096;
    const float* pb = p_bias  + (size_t)(b * NE + e) * 4096;
    const float* xfb = d_xf + b * NC * NE;
    const float* yfb = d_yf + b * NC * NE;
    uint32_t AhB = smem_to_u32(Ah), FhB = smem_to_u32(Fh);
    __half* menb = d_menh + ((size_t)b * 4096 + e * 64) * 256;

    if (t < 20) spl[t] = d_pltype[t];
    else if (t >= 32 && t < 96)  sxs[t - 32] = d_xs[b * 64 + t - 32];
    else if (t >= 96 && t < 160) syo[t - 96] = d_yo[b * 64 + t - 96];
    __syncthreads();

    // P0: logits inline + Fh <- yf
    for (int idx = t; idx < 4096; idx += 512) {
        int m = idx >> 6, n = idx & 63;
        loc[idx] = leaky(sxs[n] + syo[m]) + spl[pm[idx]] + pb[idx];
    }
    for (int idx = t; idx < 4096; idx += 512) {
        int c = idx >> 5, n2 = idx & 31;
        float2 f = *(const float2*)(yfb + c * 64 + n2 * 2);
        uint32_t off = c * 128 + ((n2 * 4) ^ ((c & 7) * 16));
        *(__half2*)((char*)Fh + off) = __floats2half2_rn(f.x, f.y);
    }
    __syncthreads();

    // P1: row stats (16 warps x 4 rows) + col stats (t<64)
    {
        int row = w * 4;
        #pragma unroll
        for (int rr = 0; rr < 4; rr++) {
            float v0 = loc[(row + rr) * 64 + lane];
            float v1 = loc[(row + rr) * 64 + 32 + lane];
            float mx = fmaxf(v0, v1);
            #pragma unroll
            for (int o = 16; o > 0; o >>= 1) mx = fmaxf(mx, __shfl_xor_sync(0xffffffff, mx, o));
            float s = __expf(v0 - mx) + __expf(v1 - mx);
            #pragma unroll
            for (int o = 16; o > 0; o >>= 1) s += __shfl_xor_sync(0xffffffff, s, o);
            if (lane == 0) { rmax[row + rr] = mx; rinv[row + rr] = 1.f / s; }
        }
    }
    if (t < 64) {
        float mx = -1e30f;
        for (int m = 0; m < 64; m++) mx = fmaxf(mx, loc[m * 64 + t]);
        float s = 0.f;
        for (int m = 0; m < 64; m++) s += __expf(loc[m * 64 + t] - mx);
        cmax[t] = mx; cinv[t] = 1.f / s;
    }
    __syncthreads();

    // P2: Ah[m][n] row softmax
    for (int idx = t; idx < 2048; idx += 512) {
        int m = idx >> 5, n2 = idx & 31;
        float v0 = __expf(loc[m * 64 + n2 * 2]     - rmax[m]) * rinv[m];
        float v1 = __expf(loc[m * 64 + n2 * 2 + 1] - rmax[m]) * rinv[m];
        uint32_t off = m * 128 + ((n2 * 4) ^ ((m & 7) * 16));
        *(__half2*)((char*)Ah + off) = __floats2half2_rn(v0, v1);
    }
    __syncthreads();

    // GEMM1: strip s = w&7 (c rows s*16..+16), half h = w>>3 (ni 4 of 8)
    int s8 = w & 7, h8 = w >> 3;
    float acc[4][4];
    #pragma unroll
    for (int ni = 0; ni < 4; ni++)
        #pragma unroll
        for (int q = 0; q < 4; q++) acc[ni][q] = 0.f;
    #pragma unroll
    for (int ks = 0; ks < 4; ks++) {
        uint32_t a[4];
        int row = s8 * 16 + (lane & 15);
        uint32_t off = row * 128 + (((ks * 16 + (lane >> 4) * 8) * 2) ^ ((row & 7) * 16));
        LDSM_X4(a[0], a[1], a[2], a[3], FhB + off);
        #pragma unroll
        for (int ni = 0; ni < 4; ni++) {
            int mr = (h8 * 4 + ni) * 8 + (lane & 7);
            uint32_t offb = mr * 128 + (((ks * 16 + ((lane >> 3) & 1) * 8) * 2) ^ ((mr & 7) * 16));
            uint32_t b0, b1;
            LDSM_X2(b0, b1, AhB + offb);
            uint32_t bf[2] = {b0, b1};
            mma16816(acc[ni], a, bf);
        }
    }
    __syncthreads();

    // stage x_ret -> Fh[m][c]
    {
        int cr = s8 * 16 + (lane >> 2);
        #pragma unroll
        for (int ni = 0; ni < 4; ni++) {
            int mc = (h8 * 4 + ni) * 8 + (lane & 3) * 2;
            float2 r0 = *(const float2*)(xfb + cr * 64 + mc);
            float2 r1 = *(const float2*)(xfb + (cr + 8) * 64 + mc);
            Fh[mc * TPITCH + cr]           = __float2half(leaky(acc[ni][0] + r0.x));
            Fh[(mc + 1) * TPITCH + cr]     = __float2half(leaky(acc[ni][1] + r0.y));
            Fh[mc * TPITCH + cr + 8]       = __float2half(leaky(acc[ni][2] + r1.x));
            Fh[(mc + 1) * TPITCH + cr + 8] = __float2half(leaky(acc[ni][3] + r1.y));
        }
    }
    __syncthreads();
    for (int idx = t; idx < 1024; idx += 512) {
        int row = idx >> 4, q = idx & 15;
        *(uint4*)(menb + (size_t)row * 256 + q * 8) = *(uint4*)&Fh[row * TPITCH + q * 8];
    }
    __syncthreads();

    // P3: A2h[n][m] col softmax; Fh <- xf
    for (int idx = t; idx < 2048; idx += 512) {
        int n = idx & 63, m2 = idx >> 6;
        float v0 = __expf(loc[(m2 * 2) * 64 + n]     - cmax[n]) * cinv[n];
        float v1 = __expf(loc[(m2 * 2 + 1) * 64 + n] - cmax[n]) * cinv[n];
        uint32_t off = n * 128 + ((m2 * 4) ^ ((n & 7) * 16));
        *(__half2*)((char*)Ah + off) = __floats2half2_rn(v0, v1);
    }
    for (int idx = t; idx < 4096; idx += 512) {
        int c = idx >> 5, n2 = idx & 31;
        float2 f = *(const float2*)(xfb + c * 64 + n2 * 2);
        uint32_t off = c * 128 + ((n2 * 4) ^ ((c & 7) * 16));
        *(__half2*)((char*)Fh + off) = __floats2half2_rn(f.x, f.y);
    }
    __syncthreads();

    // GEMM2
    #pragma unroll
    for (int ni = 0; ni < 4; ni++)
        #pragma unroll
        for (int q = 0; q < 4; q++) acc[ni][q] = 0.f;
    #pragma unroll
    for (int ks = 0; ks < 4; ks++) {
        uint32_t a[4];
        int row = s8 * 16 + (lane & 15);
        uint32_t off = row * 128 + (((ks * 16 + (lane >> 4) * 8) * 2) ^ ((row & 7) * 16));
        LDSM_X4(a[0], a[1], a[2], a[3], FhB + off);
        #pragma unroll
        for (int ni = 0; ni < 4; ni++) {
            int nr = (h8 * 4 + ni) * 8 + (lane & 7);
            uint32_t offb = nr * 128 + (((ks * 16 + ((lane >> 3) & 1) * 8) * 2) ^ ((nr & 7) * 16));
            uint32_t b0, b1;
            LDSM_X2(b0, b1, AhB + offb);
            uint32_t bf[2] = {b0, b1};
            mma16816(acc[ni], a, bf);
        }
    }
    __syncthreads();

    // stage y_ret -> Fh[n][c]
    {
        int cr = s8 * 16 + (lane >> 2);
        #pragma unroll
        for (int ni = 0; ni < 4; ni++) {
            int nc = (h8 * 4 + ni) * 8 + (lane & 3) * 2;
            float2 r0 = *(const float2*)(yfb + cr * 64 + nc);
            float2 r1 = *(const float2*)(yfb + (cr + 8) * 64 + nc);
            Fh[nc * TPITCH + cr]           = __float2half(leaky(acc[ni][0] + r0.x));
            Fh[(nc + 1) * TPITCH + cr]     = __float2half(leaky(acc[ni][1] + r0.y));
            Fh[nc * TPITCH + cr + 8]       = __float2half(leaky(acc[ni][2] + r1.x));
            Fh[(nc + 1) * TPITCH + cr + 8] = __float2half(leaky(acc[ni][3] + r1.y));
        }
    }
    __syncthreads();
    for (int idx = t; idx < 1024; idx += 512) {
        int row = idx >> 4, q = idx & 15;
        *(uint4*)(menb + (size_t)row * 256 + 128 + q * 8) = *(uint4*)&Fh[row * TPITCH + q * 8];
    }
}

// ---------------- conv1 via mma.sync ----------------
__global__ __launch_bounds__(256) void k_conv1_mma(const float* __restrict__ pre_out,
                                                   const float* __restrict__ b1) {
    __shared__ __align__(16) char smem_buf[2 * 128 * PITCH * 2];
    __half* As = (__half*)smem_buf;
    __half* Bs = (__half*)smem_buf + 128 * PITCH;
    __half* Ts = (__half*)smem_buf;
    int tid = threadIdx.x, lane = tid & 31, w = tid >> 5;
    int wm = w >> 2, wn = w & 3;
    int tile = blockIdx.x, b = blockIdx.y;
    int p0 = tile * 128;
    uint32_t smA = smem_to_u32(As), smB = smem_to_u32(Bs);
    const uint32_t* w32 = (const uint32_t*)d_w1h;
    float acc[4][4][4];
    #pragma unroll
    for (int mi = 0; mi < 4; mi++)
        #pragma unroll
        for (int ni = 0; ni < 4; ni++)
            #pragma unroll
            for (int q = 0; q < 4; q++) acc[mi][ni][q] = 0.f;

    for (int k0 = 0; k0 < 384; k0 += 64) {
        __syncthreads();
        for (int idx = tid; idx < 4096; idx += 256) {
            int row = idx >> 5, cp = idx & 31;
            *(uint32_t*)&As[row * PITCH + cp * 2] = w32[row * 192 + (k0 >> 1) + cp];
        }
        if (k0 < 256) {
            for (int idx = tid; idx < 1024; idx += 256) {
                int p = idx >> 3, q = idx & 7;
                uint4 v = *(const uint4*)(d_menh + ((size_t)b * 4096 + p0 + p) * 256 + k0 + q * 8);
                *(uint4*)&Bs[p * PITCH + q * 8] = v;
            }
        } else {
            for (int idx = tid; idx < 4096; idx += 256) {
                int kk = idx >> 6, pp = (idx & 63) * 2;
                float2 f = *(const float2*)(pre_out + ((size_t)b * 128 + (k0 - 256 + kk)) * 4096 + p0 + pp);
                Bs[pp * PITCH + kk]       = __float2half(f.x);
                Bs[(pp + 1) * PITCH + kk] = __float2half(f.y);
            }
        }
        __syncthreads();
        #pragma unroll
        for (int ks = 0; ks < 4; ks++) {
            uint32_t a[4][4], bf[4][2];
            #pragma unroll
            for (int mi = 0; mi < 4; mi++) {
                uint32_t ad = smA + ((wm * 64 + mi * 16 + (lane & 15)) * PITCH + ks * 16 + (lane >> 4) * 8) * 2;
                LDSM_X4(a[mi][0], a[mi][1], a[mi][2], a[mi][3], ad);
            }
            #pragma unroll
            for (int ni = 0; ni < 4; ni++) {
                uint32_t ad = smB + ((wn * 32 + ni * 8 + (lane & 7)) * PITCH + ks * 16 + ((lane >> 3) & 1) * 8) * 2;
                LDSM_X2(bf[ni][0], bf[ni][1], ad);
            }
            #pragma unroll
            for (int mi = 0; mi < 4; mi++)
                #pragma unroll
                for (int ni = 0; ni < 4; ni++) mma16816(acc[mi][ni], a[mi], bf[ni]);
        }
    }
    __syncthreads();

    int mrow = lane >> 2, ncol = (lane & 3) * 2;
    #pragma unroll
    for (int mi = 0; mi < 4; mi++) {
        int o = wm * 64 + mi * 16 + mrow;
        float bb0 = b1[o], bb1 = b1[o + 8];
        #pragma unroll
        for (int ni = 0; ni < 4; ni++) {
            int p = wn * 32 + ni * 8 + ncol;
            Ts[p * TPITCH + o]           = __float2half(leaky(acc[mi][ni][0] + bb0));
            Ts[(p + 1) * TPITCH + o]     = __float2half(leaky(acc[mi][ni][1] + bb0));
            Ts[p * TPITCH + o + 8]       = __float2half(leaky(acc[mi][ni][2] + bb1));
            Ts[(p + 1) * TPITCH + o + 8] = __float2half(leaky(acc[mi][ni][3] + bb1));
        }
    }
    __syncthreads();
    for (int idx = tid; idx < 2048; idx += 256) {
        int row = idx >> 4, q = idx & 15;
        *(uint4*)(d_hh + ((size_t)b * 4096 + p0 + row) * 128 + q * 8) = *(uint4*)&Ts[row * TPITCH + q * 8];
    }
}

// ---------------- conv2 3x3 via mma.sync (R8 proven version) ----------------
__global__ __launch_bounds__(256) void k_conv2_mma(const float* __restrict__ b2,
                                                   float* __restrict__ out) {
    __shared__ __align__(16) __half As[128 * PITCH];
    __shared__ __align__(16) __half Bs[128 * PITCH];
    int tid = threadIdx.x, lane = tid & 31, w = tid >> 5;
    int wm = w >> 2, wn = w & 3;
    int tile = blockIdx.x, b = blockIdx.y;
    int p0 = tile * 128;
    uint32_t smA = smem_to_u32(As), smB = smem_to_u32(Bs);
    const uint32_t* w32 = (const uint32_t*)d_w2s;
    float acc[4][4][4];
    #pragma unroll
    for (int mi = 0; mi < 4; mi++)
        #pragma unroll
        for (int ni = 0; ni < 4; ni++)
            #pragma unroll
            for (int q = 0; q < 4; q++) acc[mi][ni][q] = 0.f;

    for (int it = 0; it < 18; it++) {
        int shift = it >> 1;
        int c0 = (it & 1) * 64;
        int r = shift / 3 - 1, s = shift % 3 - 1;
        __syncthreads();
        for (int idx = tid; idx < 4096; idx += 256) {
            int row = idx >> 5, cp = idx & 31;
            *(uint32_t*)&As[row * PITCH + cp * 2] = w32[shift * 8192 + row * 64 + (c0 >> 1) + cp];
        }
        for (int idx = tid; idx < 1024; idx += 256) {
            int p = idx >> 3, q = idx & 7;
            int pix = p0 + p;
            int ii = (pix >> 6) + r;
            int jj = (pix & 63) + s;
            uint4 v = make_uint4(0u, 0u, 0u, 0u);
            if ((unsigned)ii < 64u && (unsigned)jj < 64u)
                v = *(const uint4*)(d_hh + ((size_t)b * 4096 + ii * 64 + jj) * 128 + c0 + q * 8);
            *(uint4*)&Bs[p * PITCH + q * 8] = v;
        }
        __syncthreads();
        #pragma unroll
        for (int ks = 0; ks < 4; ks++) {
            uint32_t a[4][4], bf[4][2];
            #pragma unroll
            for (int mi = 0; mi < 4; mi++) {
                uint32_t ad = smA + ((wm * 64 + mi * 16 + (lane & 15)) * PITCH + ks * 16 + (lane >> 4) * 8) * 2;
                LDSM_X4(a[mi][0], a[mi][1], a[mi][2], a[mi][3], ad);
            }
            #pragma unroll
            for (int ni = 0; ni < 4; ni++) {
                uint32_t ad = smB + ((wn * 32 + ni * 8 + (lane & 7)) * PITCH + ks * 16 + ((lane >> 3) & 1) * 8) * 2;
                LDSM_X2(bf[ni][0], bf[ni][1], ad);
            }
            #pragma unroll
            for (int mi = 0; mi < 4; mi++)
                #pragma unroll
                for (int ni = 0; ni < 4; ni++) mma16816(acc[mi][ni], a[mi], bf[ni]);
        }
    }

    int mrow = lane >> 2, ncol = (lane & 3) * 2;
    #pragma unroll
    for (int mi = 0; mi < 4; mi++) {
        int o = wm * 64 + mi * 16 + mrow;
        float bb0 = b2[o], bb1 = b2[o + 8];
        #pragma unroll
        for (int ni = 0; ni < 4; ni++) {
            int p = p0 + wn * 32 + ni * 8 + ncol;
            float* dst = out + (size_t)(b * NC + o) * 4096 + p;
            *(float2*)dst = make_float2(leaky(acc[mi][ni][0] + bb0), leaky(acc[mi][ni][1] + bb0));
            *(float2*)(dst + (size_t)8 * 4096) = make_float2(leaky(acc[mi][ni][2] + bb1), leaky(acc[mi][ni][3] + bb1));
        }
    }
}

// ---------------- scores + g (L inline from xs/yo) ----------------
__global__ void k_scoresg(const float* __restrict__ men2rel, const float* __restrict__ score_w,
                          const int* __restrict__ edge_mat, const float* __restrict__ m_bias) {
    int i = blockIdx.x, b = blockIdx.y, j = threadIdx.x;
    __shared__ float sw[128];
    sw[j] = score_w[j]; sw[j + 64] = score_w[j + 64];
    __syncthreads();
    float s = 0.f;
    #pragma unroll 8
    for (int c = 0; c < NC; c++) s += sw[c] * men2rel[((b * NC + c) * 64 + i) * 64 + j];
    int idx = (b * NE + i) * NE + j;
    float Lv = leaky(d_xs[b * 64 + j] + d_yo[b * 64 + i]);
    d_g[idx] = Lv + leaky(s) + d_eltype[edge_mat[idx]] + m_bias[idx];
}

// ---------------- x_lin / y_lin ----------------
__global__ __launch_bounds__(256) void k_lin(const float* __restrict__ x, const float* __restrict__ y,
                                             const float* __restrict__ xlw, const float* __restrict__ ylw) {
    __shared__ float wsm[64 * 129];
    int ihalf = blockIdx.x, b = blockIdx.y, z = blockIdx.z;
    const float* w  = z ? ylw : xlw;
    const float* in = z ? y : x;
    float* outp     = z ? d_ylin : d_xlin;
    int t = threadIdx.x;
    int i0b = ihalf * 64;
    for (int idx = t; idx < 64 * 128; idx += 256) {
        int ii = idx >> 7, j = idx & 127;
        wsm[ii * 129 + j] = w[(i0b + ii) * NCIN + j];
    }
    __syncthreads();
    int ig = t >> 4, mg = t & 15;
    int iL0 = ig * 4, m0 = mg * 4;
    float acc[4][4];
    #pragma unroll
    for (int u = 0; u < 4; u++)
        #pragma unroll
        for (int v = 0; v < 4; v++) acc[u][v] = 0.f;
    const float* inb = in + b * NCIN * NE;
    for (int j = 0; j < 128; j++) {
        float av[4], bv[4];
        #pragma unroll
        for (int u = 0; u < 4; u++) av[u] = wsm[(iL0 + u) * 129 + j];
        #pragma unroll
        for (int v = 0; v < 4; v++) bv[v] = inb[j * NE + m0 + v];
        #pragma unroll
        for (int u = 0; u < 4; u++)
            #pragma unroll
            for (int v = 0; v < 4; v++) acc[u][v] += av[u] * bv[v];
    }
    #pragma unroll
    for (int u = 0; u < 4; u++)
        #pragma unroll
        for (int v = 0; v < 4; v++)
            outp[(b * NE + m0 + v) * NCIN + i0b + iL0 + u] = acc[u][v];
}

// ---------------- final softmax + output GEMMs ----------------
__global__ __launch_bounds__(256) void k_final(const float* __restrict__ x, const float* __restrict__ y,
                                               float* __restrict__ out) {
    __shared__ float G[64 * 65];
    __shared__ float lin[64 * 65];
    int ihalf = blockIdx.x, b = blockIdx.y, z = blockIdx.z;
    int t = threadIdx.x;
    int i0b = ihalf * 64;
    const float* linsrc = z ? d_xlin : d_ylin;
    for (int idx = t; idx < 4096; idx += 256) {
        int n = idx >> 6, iL = idx & 63;
        lin[n * 65 + iL] = linsrc[(b * NE + n) * NCIN + i0b + iL];
    }
    if (t < 64) {
        int row = t;
        const float* gb = d_g + b * 4096;
        float mx = -1e30f;
        for (int k = 0; k < 64; k++) {
            float gv = z ? gb[k * 64 + row] : gb[row * 64 + k];
            G[row * 65 + k] = gv;
            mx = fmaxf(mx, gv);
        }
        float s = 0.f;
        for (int k = 0; k < 64; k++) { float ev = __expf(G[row * 65 + k] - mx); G[row * 65 + k] = ev; s += ev; }
        float inv = 1.f / s;
        for (int k = 0; k < 64; k++) G[row * 65 + k] *= inv;
    }
    __syncthreads();

    int ig = t >> 4, mg = t & 15;
    int iL0 = ig * 4, m0 = mg * 4;
    float acc[4][4];
    #pragma unroll
    for (int u = 0; u < 4; u++)
        #pragma unroll
        for (int v = 0; v < 4; v++) acc[u][v] = 0.f;
    for (int k = 0; k < 64; k++) {
        float av[4], bv[4];
        #pragma unroll
        for (int u = 0; u < 4; u++) av[u] = lin[k * 65 + iL0 + u];
        #pragma unroll
        for (int v = 0; v < 4; v++) bv[v] = G[(m0 + v) * 65 + k];
        #pragma unroll
        for (int u = 0; u < 4; u++)
            #pragma unroll
            for (int v = 0; v < 4; v++) acc[u][v] += av[u] * bv[v];
    }
    const float* resid = z ? y : x;
    float* outb = out + (z ? NB * NCIN * NE : 0);
    #pragma unroll
    for (int u = 0; u < 4; u++) {
        int i = i0b + iL0 + u;
        #pragma unroll
        for (int v = 0; v < 4; v++) {
            int m = m0 + v;
            outb[(b * NCIN + i) * NE + m] = acc[u][v] + resid[b * NCIN * NE + i * NE + m];
        }
    }
}

extern "C" void kernel_launch(void* const* d_in, const int* in_sizes, int n_in,
                              void* d_out, int out_size) {
    const float* x          = (const float*)d_in[0];
    const float* y          = (const float*)d_in[1];
    const float* m_bias     = (const float*)d_in[2];
    const int*   edge_mat   = (const int*)d_in[3];
    const float* p_bias     = (const float*)d_in[4];
    const int*   path_mat   = (const int*)d_in[5];
    const float* pre_out    = (const float*)d_in[6];
    const float* xc1_w      = (const float*)d_in[7];
    const float* yc1_w      = (const float*)d_in[8];
    const float* xc2_w      = (const float*)d_in[9];
    const float* xc2_b      = (const float*)d_in[10];
    const float* yc2_w      = (const float*)d_in[11];
    const float* yc2_b      = (const float*)d_in[12];
    const float* pconv_w    = (const float*)d_in[13];
    const float* econv_w    = (const float*)d_in[14];
    const float* conv1_w    = (const float*)d_in[15];
    const float* conv1_b    = (const float*)d_in[16];
    const float* conv2_w    = (const float*)d_in[17];
    const float* conv2_b    = (const float*)d_in[18];
    const float* score_w    = (const float*)d_in[19];
    const float* xlin_w     = (const float*)d_in[20];
    const float* ylin_w     = (const float*)d_in[21];
    const float* edge_table = (const float*)d_in[22];
    const float* path_table = (const float*)d_in[23];

    float* out = (float*)d_out;
    float* out_men2rel = out + 2 * NB * NCIN * NE;

    k_init<<<769, 256>>>(conv1_w, conv2_w, path_table, pconv_w, edge_table, econv_w,
                         xc1_w, yc1_w, xc2_w, yc2_w);
    { dim3 g(NB, 2); k_xfyf<<<g, 256>>>(x, y, xc1_w, yc1_w); }
    k_selfvec<<<NB, 128>>>(x, y, xc2_b, yc2_b);
    { dim3 g(NE, NB); k_attn<<<g, 512>>>(path_mat, p_bias); }
    { dim3 g(32, NB); k_conv1_mma<<<g, 256>>>(pre_out, conv1_b); }
    { dim3 g(32, NB); k_conv2_mma<<<g, 256>>>(conv2_b, out_men2rel); }
    { dim3 g(64, NB); k_scoresg<<<g, 64>>>(out_men2rel, score_w, edge_mat, m_bias); }
    { dim3 g(2, NB, 2); k_lin<<<g, 256>>>(x, y, xlin_w, ylin_w); }
    { dim3 g(2, NB, 2); k_final<<<g, 256>>>(x, y, out); }
}

// round 13
// speedup vs baseline: 1.0689x; 1.0689x over previous
#include <cuda_runtime.h>
#include <cuda_fp16.h>
#include <cstdint>

constexpr int NB = 8, NE = 64, NCIN = 128, NC = 128;

__device__ __forceinline__ float leaky(float v) { return v >= 0.f ? v : 0.1f * v; }

// ---------------- scratch (static device globals) ----------------
__device__ float  d_xf[NB * NC * NE];
__device__ float  d_yf[NB * NC * NE];
__device__ float  d_xs[NB * NE];
__device__ float  d_yo[NB * NE];
__device__ float  d_pltype[20];
__device__ float  d_eltype[10];
__device__ float  d_wx[NCIN];
__device__ float  d_wy[NCIN];
__device__ float  d_g[NB * NE * NE];
__device__ float  d_xlin[NB * NE * NCIN];
__device__ float  d_ylin[NB * NE * NCIN];
__device__ __half d_menh[NB * 4096 * 256];   // path_fea [b][pix][c]
__device__ __half d_hh[NB * 4096 * NC];      // conv1 out [b][pix][c]
__device__ __half d_w1h[NC * 384];
__device__ __half d_w2s[9 * NC * NC];

__device__ __forceinline__ uint32_t smem_to_u32(const void* p) {
    uint32_t a;
    asm("{ .reg .u64 t; cvta.to.shared.u64 t, %1; cvt.u32.u64 %0, t; }" : "=r"(a) : "l"(p));
    return a;
}
#define LDSM_X4(r0, r1, r2, r3, addr) \
    asm volatile("ldmatrix.sync.aligned.m8n8.x4.shared.b16 {%0,%1,%2,%3}, [%4];" \
        : "=r"(r0), "=r"(r1), "=r"(r2), "=r"(r3) : "r"(addr))
#define LDSM_X2(r0, r1, addr) \
    asm volatile("ldmatrix.sync.aligned.m8n8.x2.shared.b16 {%0,%1}, [%2];" \
        : "=r"(r0), "=r"(r1) : "r"(addr))
__device__ __forceinline__ void mma16816(float* c, const uint32_t* a, const uint32_t* b) {
    asm volatile("mma.sync.aligned.m16n8k16.row.col.f32.f16.f16.f32 "
                 "{%0,%1,%2,%3}, {%4,%5,%6,%7}, {%8,%9}, {%0,%1,%2,%3};"
                 : "+f"(c[0]), "+f"(c[1]), "+f"(c[2]), "+f"(c[3])
                 : "r"(a[0]), "r"(a[1]), "r"(a[2]), "r"(a[3]), "r"(b[0]), "r"(b[1]));
}
constexpr int PITCH = 72;
constexpr int TPITCH = 136;

// ---------------- merged init ----------------
__global__ void k_init(const float* __restrict__ w1, const float* __restrict__ w2,
                       const float* __restrict__ path_table, const float* __restrict__ pconv_w,
                       const float* __restrict__ edge_table, const float* __restrict__ econv_w,
                       const float* __restrict__ xc1_w, const float* __restrict__ yc1_w,
                       const float* __restrict__ xc2_w, const float* __restrict__ yc2_w) {
    int blk = blockIdx.x, t = threadIdx.x;
    if (blk < 192) {
        int i = blk * 256 + t;
        d_w1h[i] = __float2half(w1[i]);
    } else if (blk < 768) {
        int i = (blk - 192) * 256 + t;
        int shift = i / 16384, rem = i % 16384;
        int o = rem >> 7, c = rem & 127;
        d_w2s[i] = __float2half(w2[(o * NC + c) * 9 + shift]);
    } else {
        if (t < 20) {
            float s = 0.f;
            #pragma unroll
            for (int d = 0; d < 32; d++) s += path_table[t * 32 + d] * pconv_w[d];
            d_pltype[t] = leaky(s);
        }
        if (t < 10) {
            float s = 0.f;
            #pragma unroll
            for (int d = 0; d < 32; d++) s += edge_table[t * 32 + d] * econv_w[d];
            d_eltype[t] = leaky(s);
        }
        if (t < 128) {
            float ax = 0.f, ay = 0.f;
            #pragma unroll 8
            for (int c = 0; c < NC; c++) {
                ax += xc2_w[c] * xc1_w[c * NCIN + t];
                ay += yc2_w[c] * yc1_w[c * NCIN + t];
            }
            d_wx[t] = ax; d_wy[t] = ay;
        }
    }
}

// ---------------- x_f / y_f via mma.sync ----------------
__global__ __launch_bounds__(256) void k_xfyf(const float* __restrict__ x, const float* __restrict__ y,
                                              const float* __restrict__ xw, const float* __restrict__ yw) {
    __shared__ __align__(16) __half As[128 * PITCH];
    __shared__ __align__(16) __half Bs[64 * PITCH];
    int b = blockIdx.x, z = blockIdx.y;
    const float* w  = z ? yw : xw;
    const float* in = (z ? y : x) + b * NCIN * NE;
    float* outp     = (z ? d_yf : d_xf) + b * NC * NE;
    int tid = threadIdx.x, lane = tid & 31, wp = tid >> 5;
    int wm = wp >> 1, wn = wp & 1;
    uint32_t smA = smem_to_u32(As), smB = smem_to_u32(Bs);
    float acc[2][4][4];
    #pragma unroll
    for (int mi = 0; mi < 2; mi++)
        #pragma unroll
        for (int ni = 0; ni < 4; ni++)
            #pragma unroll
            for (int q = 0; q < 4; q++) acc[mi][ni][q] = 0.f;

    for (int k0 = 0; k0 < 128; k0 += 64) {
        __syncthreads();
        for (int idx = tid; idx < 4096; idx += 256) {
            int c = idx >> 5, i2 = idx & 31;
            float2 f = *(const float2*)(w + c * 128 + k0 + i2 * 2);
            *(__half2*)&As[c * PITCH + i2 * 2] = __floats2half2_rn(f.x, f.y);
        }
        for (int idx = tid; idx < 2048; idx += 256) {
            int i = idx >> 5, m2 = idx & 31;
            float2 f = *(const float2*)(in + (k0 + i) * 64 + m2 * 2);
            Bs[(m2 * 2) * PITCH + i]     = __float2half(f.x);
            Bs[(m2 * 2 + 1) * PITCH + i] = __float2half(f.y);
        }
        __syncthreads();
        #pragma unroll
        for (int ks = 0; ks < 4; ks++) {
            uint32_t a[2][4], bf[4][2];
            #pragma unroll
            for (int mi = 0; mi < 2; mi++) {
                uint32_t ad = smA + ((wm * 32 + mi * 16 + (lane & 15)) * PITCH + ks * 16 + (lane >> 4) * 8) * 2;
                LDSM_X4(a[mi][0], a[mi][1], a[mi][2], a[mi][3], ad);
            }
            #pragma unroll
            for (int ni = 0; ni < 4; ni++) {
                uint32_t ad = smB + ((wn * 32 + ni * 8 + (lane & 7)) * PITCH + ks * 16 + ((lane >> 3) & 1) * 8) * 2;
                LDSM_X2(bf[ni][0], bf[ni][1], ad);
            }
            #pragma unroll
            for (int mi = 0; mi < 2; mi++)
                #pragma unroll
                for (int ni = 0; ni < 4; ni++) mma16816(acc[mi][ni], a[mi], bf[ni]);
        }
    }
    #pragma unroll
    for (int mi = 0; mi < 2; mi++) {
        int c = wm * 32 + mi * 16 + (lane >> 2);
        #pragma unroll
        for (int ni = 0; ni < 4; ni++) {
            int m = wn * 32 + ni * 8 + (lane & 3) * 2;
            *(float2*)(outp + c * 64 + m)       = make_float2(acc[mi][ni][0], acc[mi][ni][1]);
            *(float2*)(outp + (c + 8) * 64 + m) = make_float2(acc[mi][ni][2], acc[mi][ni][3]);
        }
    }
}

// ---------------- x_self / y_other vectors ----------------
__global__ void k_selfvec(const float* __restrict__ x, const float* __restrict__ y,
                          const float* __restrict__ xc2_b, const float* __restrict__ yc2_b) {
    int b = blockIdx.x, t = threadIdx.x;
    if (t < 64) {
        const float* xb = x + b * NCIN * NE + t;
        float a0 = 0.f, a1 = 0.f;
        #pragma unroll 8
        for (int i = 0; i < NCIN; i += 2) { a0 += d_wx[i] * xb[i * NE]; a1 += d_wx[i + 1] * xb[(i + 1) * NE]; }
        d_xs[b * 64 + t] = a0 + a1 + xc2_b[0];
    } else {
        int m = t - 64;
        const float* yb = y + b * NCIN * NE + m;
        float a0 = 0.f, a1 = 0.f;
        #pragma unroll 8
        for (int i = 0; i < NCIN; i += 2) { a0 += d_wy[i] * yb[i * NE]; a1 += d_wy[i + 1] * yb[(i + 1) * NE]; }
        d_yo[b * 64 + m] = a0 + a1 + yc2_b[0];
    }
}

// ---------------- per-(b,e) path attention: R8 proven structure, inline L ----------------
__global__ __launch_bounds__(256) void k_attn(const int* __restrict__ path_mat,
                                              const float* __restrict__ p_bias) {
    __shared__ __align__(16) float  loc[64 * 64];
    __shared__ __align__(16) __half Ah[64 * 64];
    __shared__ __align__(16) __half Fh[64 * TPITCH];
    __shared__ float rmax[64], rinv[64], cmax[64], cinv[64];
    __shared__ float sxs[64], syo[64], spl[20];
    int e = blockIdx.x, b = blockIdx.y, t = threadIdx.x;
    int lane = t & 31, w = t >> 5;
    const int*   pm = path_mat + (b * NE + e) * 4096;
    const float* pb = p_bias  + (size_t)(b * NE + e) * 4096;
    const float* xfb = d_xf + b * NC * NE;
    const float* yfb = d_yf + b * NC * NE;
    uint32_t AhB = smem_to_u32(Ah), FhB = smem_to_u32(Fh);
    __half* menb = d_menh + ((size_t)b * 4096 + e * 64) * 256;

    if (t < 20) spl[t] = d_pltype[t];
    else if (t >= 32 && t < 96)  sxs[t - 32] = d_xs[b * 64 + t - 32];
    else if (t >= 96 && t < 160) syo[t - 96] = d_yo[b * 64 + t - 96];
    __syncthreads();

    for (int idx = t; idx < 4096; idx += 256) {
        int m = idx >> 6, n = idx & 63;
        loc[idx] = leaky(sxs[n] + syo[m]) + spl[pm[idx]] + pb[idx];
    }
    for (int idx = t; idx < 4096; idx += 256) {
        int c = idx >> 5, n2 = idx & 31;
        float2 f = *(const float2*)(yfb + c * 64 + n2 * 2);
        uint32_t off = c * 128 + ((n2 * 4) ^ ((c & 7) * 16));
        *(__half2*)((char*)Fh + off) = __floats2half2_rn(f.x, f.y);
    }
    __syncthreads();

    {
        int row = w * 8;
        #pragma unroll
        for (int rr = 0; rr < 8; rr++) {
            float v0 = loc[(row + rr) * 64 + lane];
            float v1 = loc[(row + rr) * 64 + 32 + lane];
            float mx = fmaxf(v0, v1);
            #pragma unroll
            for (int o = 16; o > 0; o >>= 1) mx = fmaxf(mx, __shfl_xor_sync(0xffffffff, mx, o));
            float s = __expf(v0 - mx) + __expf(v1 - mx);
            #pragma unroll
            for (int o = 16; o > 0; o >>= 1) s += __shfl_xor_sync(0xffffffff, s, o);
            if (lane == 0) { rmax[row + rr] = mx; rinv[row + rr] = 1.f / s; }
        }
    }
    if (t < 64) {
        float mx = -1e30f;
        for (int m = 0; m < 64; m++) mx = fmaxf(mx, loc[m * 64 + t]);
        float s = 0.f;
        for (int m = 0; m < 64; m++) s += __expf(loc[m * 64 + t] - mx);
        cmax[t] = mx; cinv[t] = 1.f / s;
    }
    __syncthreads();

    for (int idx = t; idx < 2048; idx += 256) {
        int m = idx >> 5, n2 = idx & 31;
        float v0 = __expf(loc[m * 64 + n2 * 2]     - rmax[m]) * rinv[m];
        float v1 = __expf(loc[m * 64 + n2 * 2 + 1] - rmax[m]) * rinv[m];
        uint32_t off = m * 128 + ((n2 * 4) ^ ((m & 7) * 16));
        *(__half2*)((char*)Ah + off) = __floats2half2_rn(v0, v1);
    }
    __syncthreads();

    float acc[8][4];
    #pragma unroll
    for (int ni = 0; ni < 8; ni++)
        #pragma unroll
        for (int q = 0; q < 4; q++) acc[ni][q] = 0.f;
    #pragma unroll
    for (int ks = 0; ks < 4; ks++) {
        uint32_t a[4];
        int row = w * 16 + (lane & 15);
        uint32_t off = row * 128 + (((ks * 16 + (lane >> 4) * 8) * 2) ^ ((row & 7) * 16));
        LDSM_X4(a[0], a[1], a[2], a[3], FhB + off);
        #pragma unroll
        for (int ni = 0; ni < 8; ni++) {
            int mr = ni * 8 + (lane & 7);
            uint32_t offb = mr * 128 + (((ks * 16 + ((lane >> 3) & 1) * 8) * 2) ^ ((mr & 7) * 16));
            uint32_t b0, b1;
            LDSM_X2(b0, b1, AhB + offb);
            uint32_t bf[2] = {b0, b1};
            mma16816(acc[ni], a, bf);
        }
    }
    __syncthreads();

    {
        int cr = w * 16 + (lane >> 2);
        #pragma unroll
        for (int ni = 0; ni < 8; ni++) {
            int mc = ni * 8 + (lane & 3) * 2;
            float2 r0 = *(const float2*)(xfb + cr * 64 + mc);
            float2 r1 = *(const float2*)(xfb + (cr + 8) * 64 + mc);
            Fh[mc * TPITCH + cr]           = __float2half(leaky(acc[ni][0] + r0.x));
            Fh[(mc + 1) * TPITCH + cr]     = __float2half(leaky(acc[ni][1] + r0.y));
            Fh[mc * TPITCH + cr + 8]       = __float2half(leaky(acc[ni][2] + r1.x));
            Fh[(mc + 1) * TPITCH + cr + 8] = __float2half(leaky(acc[ni][3] + r1.y));
        }
    }
    __syncthreads();
    for (int idx = t; idx < 1024; idx += 256) {
        int row = idx >> 4, q = idx & 15;
        *(uint4*)(menb + (size_t)row * 256 + q * 8) = *(uint4*)&Fh[row * TPITCH + q * 8];
    }
    __syncthreads();

    for (int idx = t; idx < 2048; idx += 256) {
        int n = idx & 63, m2 = idx >> 6;
        float v0 = __expf(loc[(m2 * 2) * 64 + n]     - cmax[n]) * cinv[n];
        float v1 = __expf(loc[(m2 * 2 + 1) * 64 + n] - cmax[n]) * cinv[n];
        uint32_t off = n * 128 + ((m2 * 4) ^ ((n & 7) * 16));
        *(__half2*)((char*)Ah + off) = __floats2half2_rn(v0, v1);
    }
    for (int idx = t; idx < 4096; idx += 256) {
        int c = idx >> 5, n2 = idx & 31;
        float2 f = *(const float2*)(xfb + c * 64 + n2 * 2);
        uint32_t off = c * 128 + ((n2 * 4) ^ ((c & 7) * 16));
        *(__half2*)((char*)Fh + off) = __floats2half2_rn(f.x, f.y);
    }
    __syncthreads();

    #pragma unroll
    for (int ni = 0; ni < 8; ni++)
        #pragma unroll
        for (int q = 0; q < 4; q++) acc[ni][q] = 0.f;
    #pragma unroll
    for (int ks = 0; ks < 4; ks++) {
        uint32_t a[4];
        int row = w * 16 + (lane & 15);
        uint32_t off = row * 128 + (((ks * 16 + (lane >> 4) * 8) * 2) ^ ((row & 7) * 16));
        LDSM_X4(a[0], a[1], a[2], a[3], FhB + off);
        #pragma unroll
        for (int ni = 0; ni < 8; ni++) {
            int nr = ni * 8 + (lane & 7);
            uint32_t offb = nr * 128 + (((ks * 16 + ((lane >> 3) & 1) * 8) * 2) ^ ((nr & 7) * 16));
            uint32_t b0, b1;
            LDSM_X2(b0, b1, AhB + offb);
            uint32_t bf[2] = {b0, b1};
            mma16816(acc[ni], a, bf);
        }
    }
    __syncthreads();

    {
        int cr = w * 16 + (lane >> 2);
        #pragma unroll
        for (int ni = 0; ni < 8; ni++) {
            int nc = ni * 8 + (lane & 3) * 2;
            float2 r0 = *(const float2*)(yfb + cr * 64 + nc);
            float2 r1 = *(const float2*)(yfb + (cr + 8) * 64 + nc);
            Fh[nc * TPITCH + cr]           = __float2half(leaky(acc[ni][0] + r0.x));
            Fh[(nc + 1) * TPITCH + cr]     = __float2half(leaky(acc[ni][1] + r0.y));
            Fh[nc * TPITCH + cr + 8]       = __float2half(leaky(acc[ni][2] + r1.x));
            Fh[(nc + 1) * TPITCH + cr + 8] = __float2half(leaky(acc[ni][3] + r1.y));
        }
    }
    __syncthreads();
    for (int idx = t; idx < 1024; idx += 256) {
        int row = idx >> 4, q = idx & 15;
        *(uint4*)(menb + (size_t)row * 256 + 128 + q * 8) = *(uint4*)&Fh[row * TPITCH + q * 8];
    }
}

// ---------------- conv1 via mma.sync ----------------
__global__ __launch_bounds__(256) void k_conv1_mma(const float* __restrict__ pre_out,
                                                   const float* __restrict__ b1) {
    __shared__ __align__(16) char smem_buf[2 * 128 * PITCH * 2];
    __half* As = (__half*)smem_buf;
    __half* Bs = (__half*)smem_buf + 128 * PITCH;
    __half* Ts = (__half*)smem_buf;
    int tid = threadIdx.x, lane = tid & 31, w = tid >> 5;
    int wm = w >> 2, wn = w & 3;
    int tile = blockIdx.x, b = blockIdx.y;
    int p0 = tile * 128;
    uint32_t smA = smem_to_u32(As), smB = smem_to_u32(Bs);
    const uint32_t* w32 = (const uint32_t*)d_w1h;
    float acc[4][4][4];
    #pragma unroll
    for (int mi = 0; mi < 4; mi++)
        #pragma unroll
        for (int ni = 0; ni < 4; ni++)
            #pragma unroll
            for (int q = 0; q < 4; q++) acc[mi][ni][q] = 0.f;

    for (int k0 = 0; k0 < 384; k0 += 64) {
        __syncthreads();
        for (int idx = tid; idx < 4096; idx += 256) {
            int row = idx >> 5, cp = idx & 31;
            *(uint32_t*)&As[row * PITCH + cp * 2] = w32[row * 192 + (k0 >> 1) + cp];
        }
        if (k0 < 256) {
            for (int idx = tid; idx < 1024; idx += 256) {
                int p = idx >> 3, q = idx & 7;
                uint4 v = *(const uint4*)(d_menh + ((size_t)b * 4096 + p0 + p) * 256 + k0 + q * 8);
                *(uint4*)&Bs[p * PITCH + q * 8] = v;
            }
        } else {
            for (int idx = tid; idx < 4096; idx += 256) {
                int kk = idx >> 6, pp = (idx & 63) * 2;
                float2 f = *(const float2*)(pre_out + ((size_t)b * 128 + (k0 - 256 + kk)) * 4096 + p0 + pp);
                Bs[pp * PITCH + kk]       = __float2half(f.x);
                Bs[(pp + 1) * PITCH + kk] = __float2half(f.y);
            }
        }
        __syncthreads();
        #pragma unroll
        for (int ks = 0; ks < 4; ks++) {
            uint32_t a[4][4], bf[4][2];
            #pragma unroll
            for (int mi = 0; mi < 4; mi++) {
                uint32_t ad = smA + ((wm * 64 + mi * 16 + (lane & 15)) * PITCH + ks * 16 + (lane >> 4) * 8) * 2;
                LDSM_X4(a[mi][0], a[mi][1], a[mi][2], a[mi][3], ad);
            }
            #pragma unroll
            for (int ni = 0; ni < 4; ni++) {
                uint32_t ad = smB + ((wn * 32 + ni * 8 + (lane & 7)) * PITCH + ks * 16 + ((lane >> 3) & 1) * 8) * 2;
                LDSM_X2(bf[ni][0], bf[ni][1], ad);
            }
            #pragma unroll
            for (int mi = 0; mi < 4; mi++)
                #pragma unroll
                for (int ni = 0; ni < 4; ni++) mma16816(acc[mi][ni], a[mi], bf[ni]);
        }
    }
    __syncthreads();

    int mrow = lane >> 2, ncol = (lane & 3) * 2;
    #pragma unroll
    for (int mi = 0; mi < 4; mi++) {
        int o = wm * 64 + mi * 16 + mrow;
        float bb0 = b1[o], bb1 = b1[o + 8];
        #pragma unroll
        for (int ni = 0; ni < 4; ni++) {
            int p = wn * 32 + ni * 8 + ncol;
            Ts[p * TPITCH + o]           = __float2half(leaky(acc[mi][ni][0] + bb0));
            Ts[(p + 1) * TPITCH + o]     = __float2half(leaky(acc[mi][ni][1] + bb0));
            Ts[p * TPITCH + o + 8]       = __float2half(leaky(acc[mi][ni][2] + bb1));
            Ts[(p + 1) * TPITCH + o + 8] = __float2half(leaky(acc[mi][ni][3] + bb1));
        }
    }
    __syncthreads();
    for (int idx = tid; idx < 2048; idx += 256) {
        int row = idx >> 4, q = idx & 15;
        *(uint4*)(d_hh + ((size_t)b * 4096 + p0 + row) * 128 + q * 8) = *(uint4*)&Ts[row * TPITCH + q * 8];
    }
}

// ---------------- conv2 3x3 via mma.sync ----------------
__global__ __launch_bounds__(256) void k_conv2_mma(const float* __restrict__ b2,
                                                   float* __restrict__ out) {
    __shared__ __align__(16) __half As[128 * PITCH];
    __shared__ __align__(16) __half Bs[128 * PITCH];
    int tid = threadIdx.x, lane = tid & 31, w = tid >> 5;
    int wm = w >> 2, wn = w & 3;
    int tile = blockIdx.x, b = blockIdx.y;
    int p0 = tile * 128;
    uint32_t smA = smem_to_u32(As), smB = smem_to_u32(Bs);
    const uint32_t* w32 = (const uint32_t*)d_w2s;
    float acc[4][4][4];
    #pragma unroll
    for (int mi = 0; mi < 4; mi++)
        #pragma unroll
        for (int ni = 0; ni < 4; ni++)
            #pragma unroll
            for (int q = 0; q < 4; q++) acc[mi][ni][q] = 0.f;

    for (int it = 0; it < 18; it++) {
        int shift = it >> 1;
        int c0 = (it & 1) * 64;
        int r = shift / 3 - 1, s = shift % 3 - 1;
        __syncthreads();
        for (int idx = tid; idx < 4096; idx += 256) {
            int row = idx >> 5, cp = idx & 31;
            *(uint32_t*)&As[row * PITCH + cp * 2] = w32[shift * 8192 + row * 64 + (c0 >> 1) + cp];
        }
        for (int idx = tid; idx < 1024; idx += 256) {
            int p = idx >> 3, q = idx & 7;
            int pix = p0 + p;
            int ii = (pix >> 6) + r;
            int jj = (pix & 63) + s;
            uint4 v = make_uint4(0u, 0u, 0u, 0u);
            if ((unsigned)ii < 64u && (unsigned)jj < 64u)
                v = *(const uint4*)(d_hh + ((size_t)b * 4096 + ii * 64 + jj) * 128 + c0 + q * 8);
            *(uint4*)&Bs[p * PITCH + q * 8] = v;
        }
        __syncthreads();
        #pragma unroll
        for (int ks = 0; ks < 4; ks++) {
            uint32_t a[4][4], bf[4][2];
            #pragma unroll
            for (int mi = 0; mi < 4; mi++) {
                uint32_t ad = smA + ((wm * 64 + mi * 16 + (lane & 15)) * PITCH + ks * 16 + (lane >> 4) * 8) * 2;
                LDSM_X4(a[mi][0], a[mi][1], a[mi][2], a[mi][3], ad);
            }
            #pragma unroll
            for (int ni = 0; ni < 4; ni++) {
                uint32_t ad = smB + ((wn * 32 + ni * 8 + (lane & 7)) * PITCH + ks * 16 + ((lane >> 3) & 1) * 8) * 2;
                LDSM_X2(bf[ni][0], bf[ni][1], ad);
            }
            #pragma unroll
            for (int mi = 0; mi < 4; mi++)
                #pragma unroll
                for (int ni = 0; ni < 4; ni++) mma16816(acc[mi][ni], a[mi], bf[ni]);
        }
    }

    int mrow = lane >> 2, ncol = (lane & 3) * 2;
    #pragma unroll
    for (int mi = 0; mi < 4; mi++) {
        int o = wm * 64 + mi * 16 + mrow;
        float bb0 = b2[o], bb1 = b2[o + 8];
        #pragma unroll
        for (int ni = 0; ni < 4; ni++) {
            int p = p0 + wn * 32 + ni * 8 + ncol;
            float* dst = out + (size_t)(b * NC + o) * 4096 + p;
            *(float2*)dst = make_float2(leaky(acc[mi][ni][0] + bb0), leaky(acc[mi][ni][1] + bb0));
            *(float2*)(dst + (size_t)8 * 4096) = make_float2(leaky(acc[mi][ni][2] + bb1), leaky(acc[mi][ni][3] + bb1));
        }
    }
}

// ---------------- scores + g (L inline) ----------------
__global__ void k_scoresg(const float* __restrict__ men2rel, const float* __restrict__ score_w,
                          const int* __restrict__ edge_mat, const float* __restrict__ m_bias) {
    int i = blockIdx.x, b = blockIdx.y, j = threadIdx.x;
    __shared__ float sw[128];
    sw[j] = score_w[j]; sw[j + 64] = score_w[j + 64];
    __syncthreads();
    float s = 0.f;
    #pragma unroll 8
    for (int c = 0; c < NC; c++) s += sw[c] * men2rel[((b * NC + c) * 64 + i) * 64 + j];
    int idx = (b * NE + i) * NE + j;
    float Lv = leaky(d_xs[b * 64 + j] + d_yo[b * 64 + i]);
    d_g[idx] = Lv + leaky(s) + d_eltype[edge_mat[idx]] + m_bias[idx];
}

// ---------------- x_lin / y_lin ----------------
__global__ __launch_bounds__(256) void k_lin(const float* __restrict__ x, const float* __restrict__ y,
                                             const float* __restrict__ xlw, const float* __restrict__ ylw) {
    __shared__ float wsm[64 * 129];
    int ihalf = blockIdx.x, b = blockIdx.y, z = blockIdx.z;
    const float* w  = z ? ylw : xlw;
    const float* in = z ? y : x;
    float* outp     = z ? d_ylin : d_xlin;
    int t = threadIdx.x;
    int i0b = ihalf * 64;
    for (int idx = t; idx < 64 * 128; idx += 256) {
        int ii = idx >> 7, j = idx & 127;
        wsm[ii * 129 + j] = w[(i0b + ii) * NCIN + j];
    }
    __syncthreads();
    int ig = t >> 4, mg = t & 15;
    int iL0 = ig * 4, m0 = mg * 4;
    float acc[4][4];
    #pragma unroll
    for (int u = 0; u < 4; u++)
        #pragma unroll
        for (int v = 0; v < 4; v++) acc[u][v] = 0.f;
    const float* inb = in + b * NCIN * NE;
    for (int j = 0; j < 128; j++) {
        float av[4], bv[4];
        #pragma unroll
        for (int u = 0; u < 4; u++) av[u] = wsm[(iL0 + u) * 129 + j];
        #pragma unroll
        for (int v = 0; v < 4; v++) bv[v] = inb[j * NE + m0 + v];
        #pragma unroll
        for (int u = 0; u < 4; u++)
            #pragma unroll
            for (int v = 0; v < 4; v++) acc[u][v] += av[u] * bv[v];
    }
    #pragma unroll
    for (int u = 0; u < 4; u++)
        #pragma unroll
        for (int v = 0; v < 4; v++)
            outp[(b * NE + m0 + v) * NCIN + i0b + iL0 + u] = acc[u][v];
}

// ---------------- final softmax + output GEMMs ----------------
__global__ __launch_bounds__(256) void k_final(const float* __restrict__ x, const float* __restrict__ y,
                                               float* __restrict__ out) {
    __shared__ float G[64 * 65];
    __shared__ float lin[64 * 65];
    int ihalf = blockIdx.x, b = blockIdx.y, z = blockIdx.z;
    int t = threadIdx.x;
    int i0b = ihalf * 64;
    const float* linsrc = z ? d_xlin : d_ylin;
    for (int idx = t; idx < 4096; idx += 256) {
        int n = idx >> 6, iL = idx & 63;
        lin[n * 65 + iL] = linsrc[(b * NE + n) * NCIN + i0b + iL];
    }
    if (t < 64) {
        int row = t;
        const float* gb = d_g + b * 4096;
        float mx = -1e30f;
        for (int k = 0; k < 64; k++) {
            float gv = z ? gb[k * 64 + row] : gb[row * 64 + k];
            G[row * 65 + k] = gv;
            mx = fmaxf(mx, gv);
        }
        float s = 0.f;
        for (int k = 0; k < 64; k++) { float ev = __expf(G[row * 65 + k] - mx); G[row * 65 + k] = ev; s += ev; }
        float inv = 1.f / s;
        for (int k = 0; k < 64; k++) G[row * 65 + k] *= inv;
    }
    __syncthreads();

    int ig = t >> 4, mg = t & 15;
    int iL0 = ig * 4, m0 = mg * 4;
    float acc[4][4];
    #pragma unroll
    for (int u = 0; u < 4; u++)
        #pragma unroll
        for (int v = 0; v < 4; v++) acc[u][v] = 0.f;
    for (int k = 0; k < 64; k++) {
        float av[4], bv[4];
        #pragma unroll
        for (int u = 0; u < 4; u++) av[u] = lin[k * 65 + iL0 + u];
        #pragma unroll
        for (int v = 0; v < 4; v++) bv[v] = G[(m0 + v) * 65 + k];
        #pragma unroll
        for (int u = 0; u < 4; u++)
            #pragma unroll
            for (int v = 0; v < 4; v++) acc[u][v] += av[u] * bv[v];
    }
    const float* resid = z ? y : x;
    float* outb = out + (z ? NB * NCIN * NE : 0);
    #pragma unroll
    for (int u = 0; u < 4; u++) {
        int i = i0b + iL0 + u;
        #pragma unroll
        for (int v = 0; v < 4; v++) {
            int m = m0 + v;
            outb[(b * NCIN + i) * NE + m] = acc[u][v] + resid[b * NCIN * NE + i * NE + m];
        }
    }
}

extern "C" void kernel_launch(void* const* d_in, const int* in_sizes, int n_in,
                              void* d_out, int out_size) {
    const float* x          = (const float*)d_in[0];
    const float* y          = (const float*)d_in[1];
    const float* m_bias     = (const float*)d_in[2];
    const int*   edge_mat   = (const int*)d_in[3];
    const float* p_bias     = (const float*)d_in[4];
    const int*   path_mat   = (const int*)d_in[5];
    const float* pre_out    = (const float*)d_in[6];
    const float* xc1_w      = (const float*)d_in[7];
    const float* yc1_w      = (const float*)d_in[8];
    const float* xc2_w      = (const float*)d_in[9];
    const float* xc2_b      = (const float*)d_in[10];
    const float* yc2_w      = (const float*)d_in[11];
    const float* yc2_b      = (const float*)d_in[12];
    const float* pconv_w    = (const float*)d_in[13];
    const float* econv_w    = (const float*)d_in[14];
    const float* conv1_w    = (const float*)d_in[15];
    const float* conv1_b    = (const float*)d_in[16];
    const float* conv2_w    = (const float*)d_in[17];
    const float* conv2_b    = (const float*)d_in[18];
    const float* score_w    = (const float*)d_in[19];
    const float* xlin_w     = (const float*)d_in[20];
    const float* ylin_w     = (const float*)d_in[21];
    const float* edge_table = (const float*)d_in[22];
    const float* path_table = (const float*)d_in[23];

    float* out = (float*)d_out;
    float* out_men2rel = out + 2 * NB * NCIN * NE;

    k_init<<<769, 256>>>(conv1_w, conv2_w, path_table, pconv_w, edge_table, econv_w,
                         xc1_w, yc1_w, xc2_w, yc2_w);
    { dim3 g(NB, 2); k_xfyf<<<g, 256>>>(x, y, xc1_w, yc1_w); }
    k_selfvec<<<NB, 128>>>(x, y, xc2_b, yc2_b);
    { dim3 g(NE, NB); k_attn<<<g, 256>>>(path_mat, p_bias); }
    { dim3 g(32, NB); k_conv1_mma<<<g, 256>>>(pre_out, conv1_b); }
    { dim3 g(32, NB); k_conv2_mma<<<g, 256>>>(conv2_b, out_men2rel); }
    { dim3 g(64, NB); k_scoresg<<<g, 64>>>(out_men2rel, score_w, edge_mat, m_bias); }
    { dim3 g(2, NB, 2); k_lin<<<g, 256>>>(x, y, xlin_w, ylin_w); }
    { dim3 g(2, NB, 2); k_final<<<g, 256>>>(x, y, out); }
}

// round 14
// speedup vs baseline: 1.3587x; 1.2711x over previous
#include <cuda_runtime.h>
#include <cuda_fp16.h>
#include <cstdint>

constexpr int NB = 8, NE = 64, NCIN = 128, NC = 128;

__device__ __forceinline__ float leaky(float v) { return v >= 0.f ? v : 0.1f * v; }

// ---------------- scratch (static device globals) ----------------
__device__ float  d_xf[NB * NC * NE];
__device__ float  d_yf[NB * NC * NE];
__device__ float  d_xs[NB * NE];
__device__ float  d_yo[NB * NE];
__device__ float  d_pltype[20];
__device__ float  d_eltype[10];
__device__ float  d_g[NB * NE * NE];
__device__ float  d_xlin[NB * NE * NCIN];
__device__ float  d_ylin[NB * NE * NCIN];
__device__ __half d_menh[NB * 4096 * 256];   // path_fea [b][pix][c]
__device__ __half d_hh[NB * 4096 * NC];      // conv1 out [b][pix][c]
__device__ __half d_w1h[NC * 384];
__device__ __half d_w2s[9 * NC * NC];

__device__ __forceinline__ uint32_t smem_to_u32(const void* p) {
    uint32_t a;
    asm("{ .reg .u64 t; cvta.to.shared.u64 t, %1; cvt.u32.u64 %0, t; }" : "=r"(a) : "l"(p));
    return a;
}
#define LDSM_X4(r0, r1, r2, r3, addr) \
    asm volatile("ldmatrix.sync.aligned.m8n8.x4.shared.b16 {%0,%1,%2,%3}, [%4];" \
        : "=r"(r0), "=r"(r1), "=r"(r2), "=r"(r3) : "r"(addr))
#define LDSM_X2(r0, r1, addr) \
    asm volatile("ldmatrix.sync.aligned.m8n8.x2.shared.b16 {%0,%1}, [%2];" \
        : "=r"(r0), "=r"(r1) : "r"(addr))
__device__ __forceinline__ void mma16816(float* c, const uint32_t* a, const uint32_t* b) {
    asm volatile("mma.sync.aligned.m16n8k16.row.col.f32.f16.f16.f32 "
                 "{%0,%1,%2,%3}, {%4,%5,%6,%7}, {%8,%9}, {%0,%1,%2,%3};"
                 : "+f"(c[0]), "+f"(c[1]), "+f"(c[2]), "+f"(c[3])
                 : "r"(a[0]), "r"(a[1]), "r"(a[2]), "r"(a[3]), "r"(b[0]), "r"(b[1]));
}
constexpr int PITCH = 72;
constexpr int TPITCH = 136;

// ---------------- merged front: w1h | w2s | prep+selfvec | xfyf | lin ----------------
__global__ __launch_bounds__(256) void k_front(
        const float* __restrict__ w1, const float* __restrict__ w2,
        const float* __restrict__ path_table, const float* __restrict__ pconv_w,
        const float* __restrict__ edge_table, const float* __restrict__ econv_w,
        const float* __restrict__ xc1_w, const float* __restrict__ yc1_w,
        const float* __restrict__ xc2_w, const float* __restrict__ yc2_w,
        const float* __restrict__ xc2_b, const float* __restrict__ yc2_b,
        const float* __restrict__ x, const float* __restrict__ y,
        const float* __restrict__ xlw, const float* __restrict__ ylw) {
    __shared__ __align__(16) char fbuf[33024];   // max(lin 33024, xfyf 27648, prep 1024)
    int blk = blockIdx.x, tid = threadIdx.x;

    if (blk < 192) {                               // conv1 weights -> half
        int i = blk * 256 + tid;
        d_w1h[i] = __float2half(w1[i]);
        return;
    }
    if (blk < 768) {                               // conv2 weights -> [shift][o][c] half
        int i = (blk - 192) * 256 + tid;
        int shift = i / 16384, rem = i % 16384;
        int o = rem >> 7, c = rem & 127;
        d_w2s[i] = __float2half(w2[(o * NC + c) * 9 + shift]);
        return;
    }
    if (blk == 768) {                              // per-type scalars + fused xs/yo vectors
        float* swx = (float*)fbuf;
        float* swy = (float*)fbuf + 128;
        if (tid < 20) {
            float s = 0.f;
            #pragma unroll
            for (int d = 0; d < 32; d++) s += path_table[tid * 32 + d] * pconv_w[d];
            d_pltype[tid] = leaky(s);
        }
        if (tid < 10) {
            float s = 0.f;
            #pragma unroll
            for (int d = 0; d < 32; d++) s += edge_table[tid * 32 + d] * econv_w[d];
            d_eltype[tid] = leaky(s);
        }
        if (tid < 128) {
            float ax = 0.f, ay = 0.f;
            #pragma unroll 8
            for (int c = 0; c < NC; c++) {
                ax += xc2_w[c] * xc1_w[c * NCIN + tid];
                ay += yc2_w[c] * yc1_w[c * NCIN + tid];
            }
            swx[tid] = ax; swy[tid] = ay;
        }
        __syncthreads();
        for (int task = tid; task < 1024; task += 256) {
            int b = task >> 7, u = task & 127;
            if (u < 64) {
                const float* xb = x + b * NCIN * NE + u;
                float a0 = 0.f, a1 = 0.f;
                #pragma unroll 8
                for (int i = 0; i < NCIN; i += 2) { a0 += swx[i] * xb[i * NE]; a1 += swx[i + 1] * xb[(i + 1) * NE]; }
                d_xs[b * 64 + u] = a0 + a1 + xc2_b[0];
            } else {
                int m = u - 64;
                const float* yb = y + b * NCIN * NE + m;
                float a0 = 0.f, a1 = 0.f;
                #pragma unroll 8
                for (int i = 0; i < NCIN; i += 2) { a0 += swy[i] * yb[i * NE]; a1 += swy[i + 1] * yb[(i + 1) * NE]; }
                d_yo[b * 64 + m] = a0 + a1 + yc2_b[0];
            }
        }
        return;
    }
    if (blk < 785) {                               // xfyf: 16 blocks, mma.sync
        int bi = blk - 769;
        int b = bi >> 1, z = bi & 1;
        __half* As = (__half*)fbuf;                // 128*72 halfs = 18432B
        __half* Bs = (__half*)(fbuf + 18432);      // 64*72 halfs = 9216B
        const float* w  = z ? yc1_w : xc1_w;       // placeholder; replaced below
        w = z ? yc1_w : xc1_w;
        const float* wsel = z ? yc1_w : xc1_w;
        const float* in = (z ? y : x) + b * NCIN * NE;
        float* outp     = (z ? d_yf : d_xf) + b * NC * NE;
        int lane = tid & 31, wp = tid >> 5;
        int wm = wp >> 1, wn = wp & 1;
        uint32_t smA = smem_to_u32(As), smB = smem_to_u32(Bs);
        float acc[2][4][4];
        #pragma unroll
        for (int mi = 0; mi < 2; mi++)
            #pragma unroll
            for (int ni = 0; ni < 4; ni++)
                #pragma unroll
                for (int q = 0; q < 4; q++) acc[mi][ni][q] = 0.f;
        for (int k0 = 0; k0 < 128; k0 += 64) {
            __syncthreads();
            for (int idx = tid; idx < 4096; idx += 256) {
                int c = idx >> 5, i2 = idx & 31;
                float2 f = *(const float2*)(wsel + c * 128 + k0 + i2 * 2);
                *(__half2*)&As[c * PITCH + i2 * 2] = __floats2half2_rn(f.x, f.y);
            }
            for (int idx = tid; idx < 2048; idx += 256) {
                int i = idx >> 5, m2 = idx & 31;
                float2 f = *(const float2*)(in + (k0 + i) * 64 + m2 * 2);
                Bs[(m2 * 2) * PITCH + i]     = __float2half(f.x);
                Bs[(m2 * 2 + 1) * PITCH + i] = __float2half(f.y);
            }
            __syncthreads();
            #pragma unroll
            for (int ks = 0; ks < 4; ks++) {
                uint32_t a[2][4], bf[4][2];
                #pragma unroll
                for (int mi = 0; mi < 2; mi++) {
                    uint32_t ad = smA + ((wm * 32 + mi * 16 + (lane & 15)) * PITCH + ks * 16 + (lane >> 4) * 8) * 2;
                    LDSM_X4(a[mi][0], a[mi][1], a[mi][2], a[mi][3], ad);
                }
                #pragma unroll
                for (int ni = 0; ni < 4; ni++) {
                    uint32_t ad = smB + ((wn * 32 + ni * 8 + (lane & 7)) * PITCH + ks * 16 + ((lane >> 3) & 1) * 8) * 2;
                    LDSM_X2(bf[ni][0], bf[ni][1], ad);
                }
                #pragma unroll
                for (int mi = 0; mi < 2; mi++)
                    #pragma unroll
                    for (int ni = 0; ni < 4; ni++) mma16816(acc[mi][ni], a[mi], bf[ni]);
            }
        }
        #pragma unroll
        for (int mi = 0; mi < 2; mi++) {
            int c = wm * 32 + mi * 16 + (lane >> 2);
            #pragma unroll
            for (int ni = 0; ni < 4; ni++) {
                int m = wn * 32 + ni * 8 + (lane & 3) * 2;
                *(float2*)(outp + c * 64 + m)       = make_float2(acc[mi][ni][0], acc[mi][ni][1]);
                *(float2*)(outp + (c + 8) * 64 + m) = make_float2(acc[mi][ni][2], acc[mi][ni][3]);
            }
        }
        return;
    }
    {                                              // lin: 32 blocks
        int li = blk - 785;
        int ihalf = li & 1, b = (li >> 1) & 7, z = li >> 4;
        float* wsm = (float*)fbuf;                 // 64*129 floats = 33024B
        const float* w  = z ? ylw : xlw;
        const float* in = z ? y : x;
        float* outp     = z ? d_ylin : d_xlin;
        int i0b = ihalf * 64;
        for (int idx = tid; idx < 64 * 128; idx += 256) {
            int ii = idx >> 7, j = idx & 127;
            wsm[ii * 129 + j] = w[(i0b + ii) * NCIN + j];
        }
        __syncthreads();
        int ig = tid >> 4, mg = tid & 15;
        int iL0 = ig * 4, m0 = mg * 4;
        float acc[4][4];
        #pragma unroll
        for (int u = 0; u < 4; u++)
            #pragma unroll
            for (int v = 0; v < 4; v++) acc[u][v] = 0.f;
        const float* inb = in + b * NCIN * NE;
        for (int j = 0; j < 128; j++) {
            float av[4], bv[4];
            #pragma unroll
            for (int u = 0; u < 4; u++) av[u] = wsm[(iL0 + u) * 129 + j];
            #pragma unroll
            for (int v = 0; v < 4; v++) bv[v] = inb[j * NE + m0 + v];
            #pragma unroll
            for (int u = 0; u < 4; u++)
                #pragma unroll
                for (int v = 0; v < 4; v++) acc[u][v] += av[u] * bv[v];
        }
        #pragma unroll
        for (int u = 0; u < 4; u++)
            #pragma unroll
            for (int v = 0; v < 4; v++)
                outp[(b * NE + m0 + v) * NCIN + i0b + iL0 + u] = acc[u][v];
    }
}

// ---------------- per-(b,e) path attention (R13 proven) ----------------
__global__ __launch_bounds__(256) void k_attn(const int* __restrict__ path_mat,
                                              const float* __restrict__ p_bias) {
    __shared__ __align__(16) float  loc[64 * 64];
    __shared__ __align__(16) __half Ah[64 * 64];
    __shared__ __align__(16) __half Fh[64 * TPITCH];
    __shared__ float rmax[64], rinv[64], cmax[64], cinv[64];
    __shared__ float sxs[64], syo[64], spl[20];
    int e = blockIdx.x, b = blockIdx.y, t = threadIdx.x;
    int lane = t & 31, w = t >> 5;
    const int*   pm = path_mat + (b * NE + e) * 4096;
    const float* pb = p_bias  + (size_t)(b * NE + e) * 4096;
    const float* xfb = d_xf + b * NC * NE;
    const float* yfb = d_yf + b * NC * NE;
    uint32_t AhB = smem_to_u32(Ah), FhB = smem_to_u32(Fh);
    __half* menb = d_menh + ((size_t)b * 4096 + e * 64) * 256;

    if (t < 20) spl[t] = d_pltype[t];
    else if (t >= 32 && t < 96)  sxs[t - 32] = d_xs[b * 64 + t - 32];
    else if (t >= 96 && t < 160) syo[t - 96] = d_yo[b * 64 + t - 96];
    __syncthreads();

    for (int idx = t; idx < 4096; idx += 256) {
        int m = idx >> 6, n = idx & 63;
        loc[idx] = leaky(sxs[n] + syo[m]) + spl[pm[idx]] + pb[idx];
    }
    for (int idx = t; idx < 4096; idx += 256) {
        int c = idx >> 5, n2 = idx & 31;
        float2 f = *(const float2*)(yfb + c * 64 + n2 * 2);
        uint32_t off = c * 128 + ((n2 * 4) ^ ((c & 7) * 16));
        *(__half2*)((char*)Fh + off) = __floats2half2_rn(f.x, f.y);
    }
    __syncthreads();

    {
        int row = w * 8;
        #pragma unroll
        for (int rr = 0; rr < 8; rr++) {
            float v0 = loc[(row + rr) * 64 + lane];
            float v1 = loc[(row + rr) * 64 + 32 + lane];
            float mx = fmaxf(v0, v1);
            #pragma unroll
            for (int o = 16; o > 0; o >>= 1) mx = fmaxf(mx, __shfl_xor_sync(0xffffffff, mx, o));
            float s = __expf(v0 - mx) + __expf(v1 - mx);
            #pragma unroll
            for (int o = 16; o > 0; o >>= 1) s += __shfl_xor_sync(0xffffffff, s, o);
            if (lane == 0) { rmax[row + rr] = mx; rinv[row + rr] = 1.f / s; }
        }
    }
    if (t < 64) {
        float mx = -1e30f;
        for (int m = 0; m < 64; m++) mx = fmaxf(mx, loc[m * 64 + t]);
        float s = 0.f;
        for (int m = 0; m < 64; m++) s += __expf(loc[m * 64 + t] - mx);
        cmax[t] = mx; cinv[t] = 1.f / s;
    }
    __syncthreads();

    for (int idx = t; idx < 2048; idx += 256) {
        int m = idx >> 5, n2 = idx & 31;
        float v0 = __expf(loc[m * 64 + n2 * 2]     - rmax[m]) * rinv[m];
        float v1 = __expf(loc[m * 64 + n2 * 2 + 1] - rmax[m]) * rinv[m];
        uint32_t off = m * 128 + ((n2 * 4) ^ ((m & 7) * 16));
        *(__half2*)((char*)Ah + off) = __floats2half2_rn(v0, v1);
    }
    __syncthreads();

    float acc[8][4];
    #pragma unroll
    for (int ni = 0; ni < 8; ni++)
        #pragma unroll
        for (int q = 0; q < 4; q++) acc[ni][q] = 0.f;
    #pragma unroll
    for (int ks = 0; ks < 4; ks++) {
        uint32_t a[4];
        int row = w * 16 + (lane & 15);
        uint32_t off = row * 128 + (((ks * 16 + (lane >> 4) * 8) * 2) ^ ((row & 7) * 16));
        LDSM_X4(a[0], a[1], a[2], a[3], FhB + off);
        #pragma unroll
        for (int ni = 0; ni < 8; ni++) {
            int mr = ni * 8 + (lane & 7);
            uint32_t offb = mr * 128 + (((ks * 16 + ((lane >> 3) & 1) * 8) * 2) ^ ((mr & 7) * 16));
            uint32_t b0, b1;
            LDSM_X2(b0, b1, AhB + offb);
            uint32_t bf[2] = {b0, b1};
            mma16816(acc[ni], a, bf);
        }
    }
    __syncthreads();

    {
        int cr = w * 16 + (lane >> 2);
        #pragma unroll
        for (int ni = 0; ni < 8; ni++) {
            int mc = ni * 8 + (lane & 3) * 2;
            float2 r0 = *(const float2*)(xfb + cr * 64 + mc);
            float2 r1 = *(const float2*)(xfb + (cr + 8) * 64 + mc);
            Fh[mc * TPITCH + cr]           = __float2half(leaky(acc[ni][0] + r0.x));
            Fh[(mc + 1) * TPITCH + cr]     = __float2half(leaky(acc[ni][1] + r0.y));
            Fh[mc * TPITCH + cr + 8]       = __float2half(leaky(acc[ni][2] + r1.x));
            Fh[(mc + 1) * TPITCH + cr + 8] = __float2half(leaky(acc[ni][3] + r1.y));
        }
    }
    __syncthreads();
    for (int idx = t; idx < 1024; idx += 256) {
        int row = idx >> 4, q = idx & 15;
        *(uint4*)(menb + (size_t)row * 256 + q * 8) = *(uint4*)&Fh[row * TPITCH + q * 8];
    }
    __syncthreads();

    for (int idx = t; idx < 2048; idx += 256) {
        int n = idx & 63, m2 = idx >> 6;
        float v0 = __expf(loc[(m2 * 2) * 64 + n]     - cmax[n]) * cinv[n];
        float v1 = __expf(loc[(m2 * 2 + 1) * 64 + n] - cmax[n]) * cinv[n];
        uint32_t off = n * 128 + ((m2 * 4) ^ ((n & 7) * 16));
        *(__half2*)((char*)Ah + off) = __floats2half2_rn(v0, v1);
    }
    for (int idx = t; idx < 4096; idx += 256) {
        int c = idx >> 5, n2 = idx & 31;
        float2 f = *(const float2*)(xfb + c * 64 + n2 * 2);
        uint32_t off = c * 128 + ((n2 * 4) ^ ((c & 7) * 16));
        *(__half2*)((char*)Fh + off) = __floats2half2_rn(f.x, f.y);
    }
    __syncthreads();

    #pragma unroll
    for (int ni = 0; ni < 8; ni++)
        #pragma unroll
        for (int q = 0; q < 4; q++) acc[ni][q] = 0.f;
    #pragma unroll
    for (int ks = 0; ks < 4; ks++) {
        uint32_t a[4];
        int row = w * 16 + (lane & 15);
        uint32_t off = row * 128 + (((ks * 16 + (lane >> 4) * 8) * 2) ^ ((row & 7) * 16));
        LDSM_X4(a[0], a[1], a[2], a[3], FhB + off);
        #pragma unroll
        for (int ni = 0; ni < 8; ni++) {
            int nr = ni * 8 + (lane & 7);
            uint32_t offb = nr * 128 + (((ks * 16 + ((lane >> 3) & 1) * 8) * 2) ^ ((nr & 7) * 16));
            uint32_t b0, b1;
            LDSM_X2(b0, b1, AhB + offb);
            uint32_t bf[2] = {b0, b1};
            mma16816(acc[ni], a, bf);
        }
    }
    __syncthreads();

    {
        int cr = w * 16 + (lane >> 2);
        #pragma unroll
        for (int ni = 0; ni < 8; ni++) {
            int nc = ni * 8 + (lane & 3) * 2;
            float2 r0 = *(const float2*)(yfb + cr * 64 + nc);
            float2 r1 = *(const float2*)(yfb + (cr + 8) * 64 + nc);
            Fh[nc * TPITCH + cr]           = __float2half(leaky(acc[ni][0] + r0.x));
            Fh[(nc + 1) * TPITCH + cr]     = __float2half(leaky(acc[ni][1] + r0.y));
            Fh[nc * TPITCH + cr + 8]       = __float2half(leaky(acc[ni][2] + r1.x));
            Fh[(nc + 1) * TPITCH + cr + 8] = __float2half(leaky(acc[ni][3] + r1.y));
        }
    }
    __syncthreads();
    for (int idx = t; idx < 1024; idx += 256) {
        int row = idx >> 4, q = idx & 15;
        *(uint4*)(menb + (size_t)row * 256 + 128 + q * 8) = *(uint4*)&Fh[row * TPITCH + q * 8];
    }
}

// ---------------- conv1 via mma.sync ----------------
__global__ __launch_bounds__(256) void k_conv1_mma(const float* __restrict__ pre_out,
                                                   const float* __restrict__ b1) {
    __shared__ __align__(16) char smem_buf[2 * 128 * PITCH * 2];
    __half* As = (__half*)smem_buf;
    __half* Bs = (__half*)smem_buf + 128 * PITCH;
    __half* Ts = (__half*)smem_buf;
    int tid = threadIdx.x, lane = tid & 31, w = tid >> 5;
    int wm = w >> 2, wn = w & 3;
    int tile = blockIdx.x, b = blockIdx.y;
    int p0 = tile * 128;
    uint32_t smA = smem_to_u32(As), smB = smem_to_u32(Bs);
    const uint32_t* w32 = (const uint32_t*)d_w1h;
    float acc[4][4][4];
    #pragma unroll
    for (int mi = 0; mi < 4; mi++)
        #pragma unroll
        for (int ni = 0; ni < 4; ni++)
            #pragma unroll
            for (int q = 0; q < 4; q++) acc[mi][ni][q] = 0.f;

    for (int k0 = 0; k0 < 384; k0 += 64) {
        __syncthreads();
        for (int idx = tid; idx < 4096; idx += 256) {
            int row = idx >> 5, cp = idx & 31;
            *(uint32_t*)&As[row * PITCH + cp * 2] = w32[row * 192 + (k0 >> 1) + cp];
        }
        if (k0 < 256) {
            for (int idx = tid; idx < 1024; idx += 256) {
                int p = idx >> 3, q = idx & 7;
                uint4 v = *(const uint4*)(d_menh + ((size_t)b * 4096 + p0 + p) * 256 + k0 + q * 8);
                *(uint4*)&Bs[p * PITCH + q * 8] = v;
            }
        } else {
            for (int idx = tid; idx < 4096; idx += 256) {
                int kk = idx >> 6, pp = (idx & 63) * 2;
                float2 f = *(const float2*)(pre_out + ((size_t)b * 128 + (k0 - 256 + kk)) * 4096 + p0 + pp);
                Bs[pp * PITCH + kk]       = __float2half(f.x);
                Bs[(pp + 1) * PITCH + kk] = __float2half(f.y);
            }
        }
        __syncthreads();
        #pragma unroll
        for (int ks = 0; ks < 4; ks++) {
            uint32_t a[4][4], bf[4][2];
            #pragma unroll
            for (int mi = 0; mi < 4; mi++) {
                uint32_t ad = smA + ((wm * 64 + mi * 16 + (lane & 15)) * PITCH + ks * 16 + (lane >> 4) * 8) * 2;
                LDSM_X4(a[mi][0], a[mi][1], a[mi][2], a[mi][3], ad);
            }
            #pragma unroll
            for (int ni = 0; ni < 4; ni++) {
                uint32_t ad = smB + ((wn * 32 + ni * 8 + (lane & 7)) * PITCH + ks * 16 + ((lane >> 3) & 1) * 8) * 2;
                LDSM_X2(bf[ni][0], bf[ni][1], ad);
            }
            #pragma unroll
            for (int mi = 0; mi < 4; mi++)
                #pragma unroll
                for (int ni = 0; ni < 4; ni++) mma16816(acc[mi][ni], a[mi], bf[ni]);
        }
    }
    __syncthreads();

    int mrow = lane >> 2, ncol = (lane & 3) * 2;
    #pragma unroll
    for (int mi = 0; mi < 4; mi++) {
        int o = wm * 64 + mi * 16 + mrow;
        float bb0 = b1[o], bb1 = b1[o + 8];
        #pragma unroll
        for (int ni = 0; ni < 4; ni++) {
            int p = wn * 32 + ni * 8 + ncol;
            Ts[p * TPITCH + o]           = __float2half(leaky(acc[mi][ni][0] + bb0));
            Ts[(p + 1) * TPITCH + o]     = __float2half(leaky(acc[mi][ni][1] + bb0));
            Ts[p * TPITCH + o + 8]       = __float2half(leaky(acc[mi][ni][2] + bb1));
            Ts[(p + 1) * TPITCH + o + 8] = __float2half(leaky(acc[mi][ni][3] + bb1));
        }
    }
    __syncthreads();
    for (int idx = tid; idx < 2048; idx += 256) {
        int row = idx >> 4, q = idx & 15;
        *(uint4*)(d_hh + ((size_t)b * 4096 + p0 + row) * 128 + q * 8) = *(uint4*)&Ts[row * TPITCH + q * 8];
    }
}

// ---------------- conv2 3x3 via mma.sync ----------------
__global__ __launch_bounds__(256) void k_conv2_mma(const float* __restrict__ b2,
                                                   float* __restrict__ out) {
    __shared__ __align__(16) __half As[128 * PITCH];
    __shared__ __align__(16) __half Bs[128 * PITCH];
    int tid = threadIdx.x, lane = tid & 31, w = tid >> 5;
    int wm = w >> 2, wn = w & 3;
    int tile = blockIdx.x, b = blockIdx.y;
    int p0 = tile * 128;
    uint32_t smA = smem_to_u32(As), smB = smem_to_u32(Bs);
    const uint32_t* w32 = (const uint32_t*)d_w2s;
    float acc[4][4][4];
    #pragma unroll
    for (int mi = 0; mi < 4; mi++)
        #pragma unroll
        for (int ni = 0; ni < 4; ni++)
            #pragma unroll
            for (int q = 0; q < 4; q++) acc[mi][ni][q] = 0.f;

    for (int it = 0; it < 18; it++) {
        int shift = it >> 1;
        int c0 = (it & 1) * 64;
        int r = shift / 3 - 1, s = shift % 3 - 1;
        __syncthreads();
        for (int idx = tid; idx < 4096; idx += 256) {
            int row = idx >> 5, cp = idx & 31;
            *(uint32_t*)&As[row * PITCH + cp * 2] = w32[shift * 8192 + row * 64 + (c0 >> 1) + cp];
        }
        for (int idx = tid; idx < 1024; idx += 256) {
            int p = idx >> 3, q = idx & 7;
            int pix = p0 + p;
            int ii = (pix >> 6) + r;
            int jj = (pix & 63) + s;
            uint4 v = make_uint4(0u, 0u, 0u, 0u);
            if ((unsigned)ii < 64u && (unsigned)jj < 64u)
                v = *(const uint4*)(d_hh + ((size_t)b * 4096 + ii * 64 + jj) * 128 + c0 + q * 8);
            *(uint4*)&Bs[p * PITCH + q * 8] = v;
        }
        __syncthreads();
        #pragma unroll
        for (int ks = 0; ks < 4; ks++) {
            uint32_t a[4][4], bf[4][2];
            #pragma unroll
            for (int mi = 0; mi < 4; mi++) {
                uint32_t ad = smA + ((wm * 64 + mi * 16 + (lane & 15)) * PITCH + ks * 16 + (lane >> 4) * 8) * 2;
                LDSM_X4(a[mi][0], a[mi][1], a[mi][2], a[mi][3], ad);
            }
            #pragma unroll
            for (int ni = 0; ni < 4; ni++) {
                uint32_t ad = smB + ((wn * 32 + ni * 8 + (lane & 7)) * PITCH + ks * 16 + ((lane >> 3) & 1) * 8) * 2;
                LDSM_X2(bf[ni][0], bf[ni][1], ad);
            }
            #pragma unroll
            for (int mi = 0; mi < 4; mi++)
                #pragma unroll
                for (int ni = 0; ni < 4; ni++) mma16816(acc[mi][ni], a[mi], bf[ni]);
        }
    }

    int mrow = lane >> 2, ncol = (lane & 3) * 2;
    #pragma unroll
    for (int mi = 0; mi < 4; mi++) {
        int o = wm * 64 + mi * 16 + mrow;
        float bb0 = b2[o], bb1 = b2[o + 8];
        #pragma unroll
        for (int ni = 0; ni < 4; ni++) {
            int p = p0 + wn * 32 + ni * 8 + ncol;
            float* dst = out + (size_t)(b * NC + o) * 4096 + p;
            *(float2*)dst = make_float2(leaky(acc[mi][ni][0] + bb0), leaky(acc[mi][ni][1] + bb0));
            *(float2*)(dst + (size_t)8 * 4096) = make_float2(leaky(acc[mi][ni][2] + bb1), leaky(acc[mi][ni][3] + bb1));
        }
    }
}

// ---------------- scores + g ----------------
__global__ void k_scoresg(const float* __restrict__ men2rel, const float* __restrict__ score_w,
                          const int* __restrict__ edge_mat, const float* __restrict__ m_bias) {
    int i = blockIdx.x, b = blockIdx.y, j = threadIdx.x;
    __shared__ float sw[128];
    sw[j] = score_w[j]; sw[j + 64] = score_w[j + 64];
    __syncthreads();
    float s = 0.f;
    #pragma unroll 8
    for (int c = 0; c < NC; c++) s += sw[c] * men2rel[((b * NC + c) * 64 + i) * 64 + j];
    int idx = (b * NE + i) * NE + j;
    float Lv = leaky(d_xs[b * 64 + j] + d_yo[b * 64 + i]);
    d_g[idx] = Lv + leaky(s) + d_eltype[edge_mat[idx]] + m_bias[idx];
}

// ---------------- final softmax + output GEMMs ----------------
__global__ __launch_bounds__(256) void k_final(const float* __restrict__ x, const float* __restrict__ y,
                                               float* __restrict__ out) {
    __shared__ float G[64 * 65];
    __shared__ float lin[64 * 65];
    int ihalf = blockIdx.x, b = blockIdx.y, z = blockIdx.z;
    int t = threadIdx.x;
    int i0b = ihalf * 64;
    const float* linsrc = z ? d_xlin : d_ylin;
    for (int idx = t; idx < 4096; idx += 256) {
        int n = idx >> 6, iL = idx & 63;
        lin[n * 65 + iL] = linsrc[(b * NE + n) * NCIN + i0b + iL];
    }
    if (t < 64) {
        int row = t;
        const float* gb = d_g + b * 4096;
        float mx = -1e30f;
        for (int k = 0; k < 64; k++) {
            float gv = z ? gb[k * 64 + row] : gb[row * 64 + k];
            G[row * 65 + k] = gv;
            mx = fmaxf(mx, gv);
        }
        float s = 0.f;
        for (int k = 0; k < 64; k++) { float ev = __expf(G[row * 65 + k] - mx); G[row * 65 + k] = ev; s += ev; }
        float inv = 1.f / s;
        for (int k = 0; k < 64; k++) G[row * 65 + k] *= inv;
    }
    __syncthreads();

    int ig = t >> 4, mg = t & 15;
    int iL0 = ig * 4, m0 = mg * 4;
    float acc[4][4];
    #pragma unroll
    for (int u = 0; u < 4; u++)
        #pragma unroll
        for (int v = 0; v < 4; v++) acc[u][v] = 0.f;
    for (int k = 0; k < 64; k++) {
        float av[4], bv[4];
        #pragma unroll
        for (int u = 0; u < 4; u++) av[u] = lin[k * 65 + iL0 + u];
        #pragma unroll
        for (int v = 0; v < 4; v++) bv[v] = G[(m0 + v) * 65 + k];
        #pragma unroll
        for (int u = 0; u < 4; u++)
            #pragma unroll
            for (int v = 0; v < 4; v++) acc[u][v] += av[u] * bv[v];
    }
    const float* resid = z ? y : x;
    float* outb = out + (z ? NB * NCIN * NE : 0);
    #pragma unroll
    for (int u = 0; u < 4; u++) {
        int i = i0b + iL0 + u;
        #pragma unroll
        for (int v = 0; v < 4; v++) {
            int m = m0 + v;
            outb[(b * NCIN + i) * NE + m] = acc[u][v] + resid[b * NCIN * NE + i * NE + m];
        }
    }
}

extern "C" void kernel_launch(void* const* d_in, const int* in_sizes, int n_in,
                              void* d_out, int out_size) {
    const float* x          = (const float*)d_in[0];
    const float* y          = (const float*)d_in[1];
    const float* m_bias     = (const float*)d_in[2];
    const int*   edge_mat   = (const int*)d_in[3];
    const float* p_bias     = (const float*)d_in[4];
    const int*   path_mat   = (const int*)d_in[5];
    const float* pre_out    = (const float*)d_in[6];
    const float* xc1_w      = (const float*)d_in[7];
    const float* yc1_w      = (const float*)d_in[8];
    const float* xc2_w      = (const float*)d_in[9];
    const float* xc2_b      = (const float*)d_in[10];
    const float* yc2_w      = (const float*)d_in[11];
    const float* yc2_b      = (const float*)d_in[12];
    const float* pconv_w    = (const float*)d_in[13];
    const float* econv_w    = (const float*)d_in[14];
    const float* conv1_w    = (const float*)d_in[15];
    const float* conv1_b    = (const float*)d_in[16];
    const float* conv2_w    = (const float*)d_in[17];
    const float* conv2_b    = (const float*)d_in[18];
    const float* score_w    = (const float*)d_in[19];
    const float* xlin_w     = (const float*)d_in[20];
    const float* ylin_w     = (const float*)d_in[21];
    const float* edge_table = (const float*)d_in[22];
    const float* path_table = (const float*)d_in[23];

    float* out = (float*)d_out;
    float* out_men2rel = out + 2 * NB * NCIN * NE;

    k_front<<<817, 256>>>(conv1_w, conv2_w, path_table, pconv_w, edge_table, econv_w,
                          xc1_w, yc1_w, xc2_w, yc2_w, xc2_b, yc2_b, x, y, xlin_w, ylin_w);
    { dim3 g(NE, NB); k_attn<<<g, 256>>>(path_mat, p_bias); }
    { dim3 g(32, NB); k_conv1_mma<<<g, 256>>>(pre_out, conv1_b); }
    { dim3 g(32, NB); k_conv2_mma<<<g, 256>>>(conv2_b, out_men2rel); }
    { dim3 g(64, NB); k_scoresg<<<g, 64>>>(out_men2rel, score_w, edge_mat, m_bias); }
    { dim3 g(2, NB, 2); k_final<<<g, 256>>>(x, y, out); }
}

// round 15
// speedup vs baseline: 1.4356x; 1.0566x over previous
#include <cuda_runtime.h>
#include <cuda_fp16.h>
#include <cstdint>

constexpr int NB = 8, NE = 64, NCIN = 128, NC = 128;

__device__ __forceinline__ float leaky(float v) { return v >= 0.f ? v : 0.1f * v; }

// ---------------- scratch (static device globals) ----------------
__device__ float  d_xf[NB * NC * NE];
__device__ float  d_yf[NB * NC * NE];
__device__ float  d_xs[NB * NE];
__device__ float  d_yo[NB * NE];
__device__ float  d_pltype[20];
__device__ float  d_eltype[10];
__device__ float  d_g[NB * NE * NE];
__device__ float  d_xlin[NB * NE * NCIN];
__device__ float  d_ylin[NB * NE * NCIN];
__device__ __half d_menh[NB * 4096 * 256];   // path_fea [b][pix][c]
__device__ __half d_hh[NB * 4096 * NC];      // conv1 out [b][pix][c]
__device__ __half d_w1h[NC * 384];
__device__ __half d_w2s[9 * NC * NC];

__device__ __forceinline__ uint32_t smem_to_u32(const void* p) {
    uint32_t a;
    asm("{ .reg .u64 t; cvta.to.shared.u64 t, %1; cvt.u32.u64 %0, t; }" : "=r"(a) : "l"(p));
    return a;
}
#define LDSM_X4(r0, r1, r2, r3, addr) \
    asm volatile("ldmatrix.sync.aligned.m8n8.x4.shared.b16 {%0,%1,%2,%3}, [%4];" \
        : "=r"(r0), "=r"(r1), "=r"(r2), "=r"(r3) : "r"(addr))
#define LDSM_X2(r0, r1, addr) \
    asm volatile("ldmatrix.sync.aligned.m8n8.x2.shared.b16 {%0,%1}, [%2];" \
        : "=r"(r0), "=r"(r1) : "r"(addr))
__device__ __forceinline__ void mma16816(float* c, const uint32_t* a, const uint32_t* b) {
    asm volatile("mma.sync.aligned.m16n8k16.row.col.f32.f16.f16.f32 "
                 "{%0,%1,%2,%3}, {%4,%5,%6,%7}, {%8,%9}, {%0,%1,%2,%3};"
                 : "+f"(c[0]), "+f"(c[1]), "+f"(c[2]), "+f"(c[3])
                 : "r"(a[0]), "r"(a[1]), "r"(a[2]), "r"(a[3]), "r"(b[0]), "r"(b[1]));
}
constexpr int PITCH = 72;
constexpr int TPITCH = 136;
constexpr int P2 = 40;   // conv2 tile pitch (80B rows; ldmatrix conflict-free)

// ---------------- merged front: w1h | w2s | prep+selfvec | xfyf | lin ----------------
__global__ __launch_bounds__(256) void k_front(
        const float* __restrict__ w1, const float* __restrict__ w2,
        const float* __restrict__ path_table, const float* __restrict__ pconv_w,
        const float* __restrict__ edge_table, const float* __restrict__ econv_w,
        const float* __restrict__ xc1_w, const float* __restrict__ yc1_w,
        const float* __restrict__ xc2_w, const float* __restrict__ yc2_w,
        const float* __restrict__ xc2_b, const float* __restrict__ yc2_b,
        const float* __restrict__ x, const float* __restrict__ y,
        const float* __restrict__ xlw, const float* __restrict__ ylw) {
    __shared__ __align__(16) char fbuf[33024];
    int blk = blockIdx.x, tid = threadIdx.x;

    if (blk < 192) {
        int i = blk * 256 + tid;
        d_w1h[i] = __float2half(w1[i]);
        return;
    }
    if (blk < 768) {
        int i = (blk - 192) * 256 + tid;
        int shift = i / 16384, rem = i % 16384;
        int o = rem >> 7, c = rem & 127;
        d_w2s[i] = __float2half(w2[(o * NC + c) * 9 + shift]);
        return;
    }
    if (blk == 768) {
        float* swx = (float*)fbuf;
        float* swy = (float*)fbuf + 128;
        if (tid < 20) {
            float s = 0.f;
            #pragma unroll
            for (int d = 0; d < 32; d++) s += path_table[tid * 32 + d] * pconv_w[d];
            d_pltype[tid] = leaky(s);
        }
        if (tid < 10) {
            float s = 0.f;
            #pragma unroll
            for (int d = 0; d < 32; d++) s += edge_table[tid * 32 + d] * econv_w[d];
            d_eltype[tid] = leaky(s);
        }
        if (tid < 128) {
            float ax = 0.f, ay = 0.f;
            #pragma unroll 8
            for (int c = 0; c < NC; c++) {
                ax += xc2_w[c] * xc1_w[c * NCIN + tid];
                ay += yc2_w[c] * yc1_w[c * NCIN + tid];
            }
            swx[tid] = ax; swy[tid] = ay;
        }
        __syncthreads();
        for (int task = tid; task < 1024; task += 256) {
            int b = task >> 7, u = task & 127;
            if (u < 64) {
                const float* xb = x + b * NCIN * NE + u;
                float a0 = 0.f, a1 = 0.f;
                #pragma unroll 8
                for (int i = 0; i < NCIN; i += 2) { a0 += swx[i] * xb[i * NE]; a1 += swx[i + 1] * xb[(i + 1) * NE]; }
                d_xs[b * 64 + u] = a0 + a1 + xc2_b[0];
            } else {
                int m = u - 64;
                const float* yb = y + b * NCIN * NE + m;
                float a0 = 0.f, a1 = 0.f;
                #pragma unroll 8
                for (int i = 0; i < NCIN; i += 2) { a0 += swy[i] * yb[i * NE]; a1 += swy[i + 1] * yb[(i + 1) * NE]; }
                d_yo[b * 64 + m] = a0 + a1 + yc2_b[0];
            }
        }
        return;
    }
    if (blk < 785) {                               // xfyf: 16 blocks
        int bi = blk - 769;
        int b = bi >> 1, z = bi & 1;
        __half* As = (__half*)fbuf;
        __half* Bs = (__half*)(fbuf + 18432);
        const float* wsel = z ? yc1_w : xc1_w;
        const float* in = (z ? y : x) + b * NCIN * NE;
        float* outp     = (z ? d_yf : d_xf) + b * NC * NE;
        int lane = tid & 31, wp = tid >> 5;
        int wm = wp >> 1, wn = wp & 1;
        uint32_t smA = smem_to_u32(As), smB = smem_to_u32(Bs);
        float acc[2][4][4];
        #pragma unroll
        for (int mi = 0; mi < 2; mi++)
            #pragma unroll
            for (int ni = 0; ni < 4; ni++)
                #pragma unroll
                for (int q = 0; q < 4; q++) acc[mi][ni][q] = 0.f;
        for (int k0 = 0; k0 < 128; k0 += 64) {
            __syncthreads();
            for (int idx = tid; idx < 4096; idx += 256) {
                int c = idx >> 5, i2 = idx & 31;
                float2 f = *(const float2*)(wsel + c * 128 + k0 + i2 * 2);
                *(__half2*)&As[c * PITCH + i2 * 2] = __floats2half2_rn(f.x, f.y);
            }
            for (int idx = tid; idx < 2048; idx += 256) {
                int i = idx >> 5, m2 = idx & 31;
                float2 f = *(const float2*)(in + (k0 + i) * 64 + m2 * 2);
                Bs[(m2 * 2) * PITCH + i]     = __float2half(f.x);
                Bs[(m2 * 2 + 1) * PITCH + i] = __float2half(f.y);
            }
            __syncthreads();
            #pragma unroll
            for (int ks = 0; ks < 4; ks++) {
                uint32_t a[2][4], bf[4][2];
                #pragma unroll
                for (int mi = 0; mi < 2; mi++) {
                    uint32_t ad = smA + ((wm * 32 + mi * 16 + (lane & 15)) * PITCH + ks * 16 + (lane >> 4) * 8) * 2;
                    LDSM_X4(a[mi][0], a[mi][1], a[mi][2], a[mi][3], ad);
                }
                #pragma unroll
                for (int ni = 0; ni < 4; ni++) {
                    uint32_t ad = smB + ((wn * 32 + ni * 8 + (lane & 7)) * PITCH + ks * 16 + ((lane >> 3) & 1) * 8) * 2;
                    LDSM_X2(bf[ni][0], bf[ni][1], ad);
                }
                #pragma unroll
                for (int mi = 0; mi < 2; mi++)
                    #pragma unroll
                    for (int ni = 0; ni < 4; ni++) mma16816(acc[mi][ni], a[mi], bf[ni]);
            }
        }
        #pragma unroll
        for (int mi = 0; mi < 2; mi++) {
            int c = wm * 32 + mi * 16 + (lane >> 2);
            #pragma unroll
            for (int ni = 0; ni < 4; ni++) {
                int m = wn * 32 + ni * 8 + (lane & 3) * 2;
                *(float2*)(outp + c * 64 + m)       = make_float2(acc[mi][ni][0], acc[mi][ni][1]);
                *(float2*)(outp + (c + 8) * 64 + m) = make_float2(acc[mi][ni][2], acc[mi][ni][3]);
            }
        }
        return;
    }
    {                                              // lin: 32 blocks
        int li = blk - 785;
        int ihalf = li & 1, b = (li >> 1) & 7, z = li >> 4;
        float* wsm = (float*)fbuf;
        const float* w  = z ? ylw : xlw;
        const float* in = z ? y : x;
        float* outp     = z ? d_ylin : d_xlin;
        int i0b = ihalf * 64;
        for (int idx = tid; idx < 64 * 128; idx += 256) {
            int ii = idx >> 7, j = idx & 127;
            wsm[ii * 129 + j] = w[(i0b + ii) * NCIN + j];
        }
        __syncthreads();
        int ig = tid >> 4, mg = tid & 15;
        int iL0 = ig * 4, m0 = mg * 4;
        float acc[4][4];
        #pragma unroll
        for (int u = 0; u < 4; u++)
            #pragma unroll
            for (int v = 0; v < 4; v++) acc[u][v] = 0.f;
        const float* inb = in + b * NCIN * NE;
        for (int j = 0; j < 128; j++) {
            float av[4], bv[4];
            #pragma unroll
            for (int u = 0; u < 4; u++) av[u] = wsm[(iL0 + u) * 129 + j];
            #pragma unroll
            for (int v = 0; v < 4; v++) bv[v] = inb[j * NE + m0 + v];
            #pragma unroll
            for (int u = 0; u < 4; u++)
                #pragma unroll
                for (int v = 0; v < 4; v++) acc[u][v] += av[u] * bv[v];
        }
        #pragma unroll
        for (int u = 0; u < 4; u++)
            #pragma unroll
            for (int v = 0; v < 4; v++)
                outp[(b * NE + m0 + v) * NCIN + i0b + iL0 + u] = acc[u][v];
    }
}

// ---------------- per-(b,e) path attention (R13/R14 proven) ----------------
__global__ __launch_bounds__(256) void k_attn(const int* __restrict__ path_mat,
                                              const float* __restrict__ p_bias) {
    __shared__ __align__(16) float  loc[64 * 64];
    __shared__ __align__(16) __half Ah[64 * 64];
    __shared__ __align__(16) __half Fh[64 * TPITCH];
    __shared__ float rmax[64], rinv[64], cmax[64], cinv[64];
    __shared__ float sxs[64], syo[64], spl[20];
    int e = blockIdx.x, b = blockIdx.y, t = threadIdx.x;
    int lane = t & 31, w = t >> 5;
    const int*   pm = path_mat + (b * NE + e) * 4096;
    const float* pb = p_bias  + (size_t)(b * NE + e) * 4096;
    const float* xfb = d_xf + b * NC * NE;
    const float* yfb = d_yf + b * NC * NE;
    uint32_t AhB = smem_to_u32(Ah), FhB = smem_to_u32(Fh);
    __half* menb = d_menh + ((size_t)b * 4096 + e * 64) * 256;

    if (t < 20) spl[t] = d_pltype[t];
    else if (t >= 32 && t < 96)  sxs[t - 32] = d_xs[b * 64 + t - 32];
    else if (t >= 96 && t < 160) syo[t - 96] = d_yo[b * 64 + t - 96];
    __syncthreads();

    for (int idx = t; idx < 4096; idx += 256) {
        int m = idx >> 6, n = idx & 63;
        loc[idx] = leaky(sxs[n] + syo[m]) + spl[pm[idx]] + pb[idx];
    }
    for (int idx = t; idx < 4096; idx += 256) {
        int c = idx >> 5, n2 = idx & 31;
        float2 f = *(const float2*)(yfb + c * 64 + n2 * 2);
        uint32_t off = c * 128 + ((n2 * 4) ^ ((c & 7) * 16));
        *(__half2*)((char*)Fh + off) = __floats2half2_rn(f.x, f.y);
    }
    __syncthreads();

    {
        int row = w * 8;
        #pragma unroll
        for (int rr = 0; rr < 8; rr++) {
            float v0 = loc[(row + rr) * 64 + lane];
            float v1 = loc[(row + rr) * 64 + 32 + lane];
            float mx = fmaxf(v0, v1);
            #pragma unroll
            for (int o = 16; o > 0; o >>= 1) mx = fmaxf(mx, __shfl_xor_sync(0xffffffff, mx, o));
            float s = __expf(v0 - mx) + __expf(v1 - mx);
            #pragma unroll
            for (int o = 16; o > 0; o >>= 1) s += __shfl_xor_sync(0xffffffff, s, o);
            if (lane == 0) { rmax[row + rr] = mx; rinv[row + rr] = 1.f / s; }
        }
    }
    if (t < 64) {
        float mx = -1e30f;
        for (int m = 0; m < 64; m++) mx = fmaxf(mx, loc[m * 64 + t]);
        float s = 0.f;
        for (int m = 0; m < 64; m++) s += __expf(loc[m * 64 + t] - mx);
        cmax[t] = mx; cinv[t] = 1.f / s;
    }
    __syncthreads();

    for (int idx = t; idx < 2048; idx += 256) {
        int m = idx >> 5, n2 = idx & 31;
        float v0 = __expf(loc[m * 64 + n2 * 2]     - rmax[m]) * rinv[m];
        float v1 = __expf(loc[m * 64 + n2 * 2 + 1] - rmax[m]) * rinv[m];
        uint32_t off = m * 128 + ((n2 * 4) ^ ((m & 7) * 16));
        *(__half2*)((char*)Ah + off) = __floats2half2_rn(v0, v1);
    }
    __syncthreads();

    float acc[8][4];
    #pragma unroll
    for (int ni = 0; ni < 8; ni++)
        #pragma unroll
        for (int q = 0; q < 4; q++) acc[ni][q] = 0.f;
    #pragma unroll
    for (int ks = 0; ks < 4; ks++) {
        uint32_t a[4];
        int row = w * 16 + (lane & 15);
        uint32_t off = row * 128 + (((ks * 16 + (lane >> 4) * 8) * 2) ^ ((row & 7) * 16));
        LDSM_X4(a[0], a[1], a[2], a[3], FhB + off);
        #pragma unroll
        for (int ni = 0; ni < 8; ni++) {
            int mr = ni * 8 + (lane & 7);
            uint32_t offb = mr * 128 + (((ks * 16 + ((lane >> 3) & 1) * 8) * 2) ^ ((mr & 7) * 16));
            uint32_t b0, b1;
            LDSM_X2(b0, b1, AhB + offb);
            uint32_t bf[2] = {b0, b1};
            mma16816(acc[ni], a, bf);
        }
    }
    __syncthreads();

    {
        int cr = w * 16 + (lane >> 2);
        #pragma unroll
        for (int ni = 0; ni < 8; ni++) {
            int mc = ni * 8 + (lane & 3) * 2;
            float2 r0 = *(const float2*)(xfb + cr * 64 + mc);
            float2 r1 = *(const float2*)(xfb + (cr + 8) * 64 + mc);
            Fh[mc * TPITCH + cr]           = __float2half(leaky(acc[ni][0] + r0.x));
            Fh[(mc + 1) * TPITCH + cr]     = __float2half(leaky(acc[ni][1] + r0.y));
            Fh[mc * TPITCH + cr + 8]       = __float2half(leaky(acc[ni][2] + r1.x));
            Fh[(mc + 1) * TPITCH + cr + 8] = __float2half(leaky(acc[ni][3] + r1.y));
        }
    }
    __syncthreads();
    for (int idx = t; idx < 1024; idx += 256) {
        int row = idx >> 4, q = idx & 15;
        *(uint4*)(menb + (size_t)row * 256 + q * 8) = *(uint4*)&Fh[row * TPITCH + q * 8];
    }
    __syncthreads();

    for (int idx = t; idx < 2048; idx += 256) {
        int n = idx & 63, m2 = idx >> 6;
        float v0 = __expf(loc[(m2 * 2) * 64 + n]     - cmax[n]) * cinv[n];
        float v1 = __expf(loc[(m2 * 2 + 1) * 64 + n] - cmax[n]) * cinv[n];
        uint32_t off = n * 128 + ((m2 * 4) ^ ((n & 7) * 16));
        *(__half2*)((char*)Ah + off) = __floats2half2_rn(v0, v1);
    }
    for (int idx = t; idx < 4096; idx += 256) {
        int c = idx >> 5, n2 = idx & 31;
        float2 f = *(const float2*)(xfb + c * 64 + n2 * 2);
        uint32_t off = c * 128 + ((n2 * 4) ^ ((c & 7) * 16));
        *(__half2*)((char*)Fh + off) = __floats2half2_rn(f.x, f.y);
    }
    __syncthreads();

    #pragma unroll
    for (int ni = 0; ni < 8; ni++)
        #pragma unroll
        for (int q = 0; q < 4; q++) acc[ni][q] = 0.f;
    #pragma unroll
    for (int ks = 0; ks < 4; ks++) {
        uint32_t a[4];
        int row = w * 16 + (lane & 15);
        uint32_t off = row * 128 + (((ks * 16 + (lane >> 4) * 8) * 2) ^ ((row & 7) * 16));
        LDSM_X4(a[0], a[1], a[2], a[3], FhB + off);
        #pragma unroll
        for (int ni = 0; ni < 8; ni++) {
            int nr = ni * 8 + (lane & 7);
            uint32_t offb = nr * 128 + (((ks * 16 + ((lane >> 3) & 1) * 8) * 2) ^ ((nr & 7) * 16));
            uint32_t b0, b1;
            LDSM_X2(b0, b1, AhB + offb);
            uint32_t bf[2] = {b0, b1};
            mma16816(acc[ni], a, bf);
        }
    }
    __syncthreads();

    {
        int cr = w * 16 + (lane >> 2);
        #pragma unroll
        for (int ni = 0; ni < 8; ni++) {
            int nc = ni * 8 + (lane & 3) * 2;
            float2 r0 = *(const float2*)(yfb + cr * 64 + nc);
            float2 r1 = *(const float2*)(yfb + (cr + 8) * 64 + nc);
            Fh[nc * TPITCH + cr]           = __float2half(leaky(acc[ni][0] + r0.x));
            Fh[(nc + 1) * TPITCH + cr]     = __float2half(leaky(acc[ni][1] + r0.y));
            Fh[nc * TPITCH + cr + 8]       = __float2half(leaky(acc[ni][2] + r1.x));
            Fh[(nc + 1) * TPITCH + cr + 8] = __float2half(leaky(acc[ni][3] + r1.y));
        }
    }
    __syncthreads();
    for (int idx = t; idx < 1024; idx += 256) {
        int row = idx >> 4, q = idx & 15;
        *(uint4*)(menb + (size_t)row * 256 + 128 + q * 8) = *(uint4*)&Fh[row * TPITCH + q * 8];
    }
}

// ---------------- conv1 via mma.sync (R14 proven) ----------------
__global__ __launch_bounds__(256) void k_conv1_mma(const float* __restrict__ pre_out,
                                                   const float* __restrict__ b1) {
    __shared__ __align__(16) char smem_buf[2 * 128 * PITCH * 2];
    __half* As = (__half*)smem_buf;
    __half* Bs = (__half*)smem_buf + 128 * PITCH;
    __half* Ts = (__half*)smem_buf;
    int tid = threadIdx.x, lane = tid & 31, w = tid >> 5;
    int wm = w >> 2, wn = w & 3;
    int tile = blockIdx.x, b = blockIdx.y;
    int p0 = tile * 128;
    uint32_t smA = smem_to_u32(As), smB = smem_to_u32(Bs);
    const uint32_t* w32 = (const uint32_t*)d_w1h;
    float acc[4][4][4];
    #pragma unroll
    for (int mi = 0; mi < 4; mi++)
        #pragma unroll
        for (int ni = 0; ni < 4; ni++)
            #pragma unroll
            for (int q = 0; q < 4; q++) acc[mi][ni][q] = 0.f;

    for (int k0 = 0; k0 < 384; k0 += 64) {
        __syncthreads();
        for (int idx = tid; idx < 4096; idx += 256) {
            int row = idx >> 5, cp = idx & 31;
            *(uint32_t*)&As[row * PITCH + cp * 2] = w32[row * 192 + (k0 >> 1) + cp];
        }
        if (k0 < 256) {
            for (int idx = tid; idx < 1024; idx += 256) {
                int p = idx >> 3, q = idx & 7;
                uint4 v = *(const uint4*)(d_menh + ((size_t)b * 4096 + p0 + p) * 256 + k0 + q * 8);
                *(uint4*)&Bs[p * PITCH + q * 8] = v;
            }
        } else {
            for (int idx = tid; idx < 4096; idx += 256) {
                int kk = idx >> 6, pp = (idx & 63) * 2;
                float2 f = *(const float2*)(pre_out + ((size_t)b * 128 + (k0 - 256 + kk)) * 4096 + p0 + pp);
                Bs[pp * PITCH + kk]       = __float2half(f.x);
                Bs[(pp + 1) * PITCH + kk] = __float2half(f.y);
            }
        }
        __syncthreads();
        #pragma unroll
        for (int ks = 0; ks < 4; ks++) {
            uint32_t a[4][4], bf[4][2];
            #pragma unroll
            for (int mi = 0; mi < 4; mi++) {
                uint32_t ad = smA + ((wm * 64 + mi * 16 + (lane & 15)) * PITCH + ks * 16 + (lane >> 4) * 8) * 2;
                LDSM_X4(a[mi][0], a[mi][1], a[mi][2], a[mi][3], ad);
            }
            #pragma unroll
            for (int ni = 0; ni < 4; ni++) {
                uint32_t ad = smB + ((wn * 32 + ni * 8 + (lane & 7)) * PITCH + ks * 16 + ((lane >> 3) & 1) * 8) * 2;
                LDSM_X2(bf[ni][0], bf[ni][1], ad);
            }
            #pragma unroll
            for (int mi = 0; mi < 4; mi++)
                #pragma unroll
                for (int ni = 0; ni < 4; ni++) mma16816(acc[mi][ni], a[mi], bf[ni]);
        }
    }
    __syncthreads();

    int mrow = lane >> 2, ncol = (lane & 3) * 2;
    #pragma unroll
    for (int mi = 0; mi < 4; mi++) {
        int o = wm * 64 + mi * 16 + mrow;
        float bb0 = b1[o], bb1 = b1[o + 8];
        #pragma unroll
        for (int ni = 0; ni < 4; ni++) {
            int p = wn * 32 + ni * 8 + ncol;
            Ts[p * TPITCH + o]           = __float2half(leaky(acc[mi][ni][0] + bb0));
            Ts[(p + 1) * TPITCH + o]     = __float2half(leaky(acc[mi][ni][1] + bb0));
            Ts[p * TPITCH + o + 8]       = __float2half(leaky(acc[mi][ni][2] + bb1));
            Ts[(p + 1) * TPITCH + o + 8] = __float2half(leaky(acc[mi][ni][3] + bb1));
        }
    }
    __syncthreads();
    for (int idx = tid; idx < 2048; idx += 256) {
        int row = idx >> 4, q = idx & 15;
        *(uint4*)(d_hh + ((size_t)b * 4096 + p0 + row) * 128 + q * 8) = *(uint4*)&Ts[row * TPITCH + q * 8];
    }
}

// ---------------- conv2 3x3: register-staged double-buffered pipeline ----------------
__global__ __launch_bounds__(256) void k_conv2_mma(const float* __restrict__ b2,
                                                   float* __restrict__ out) {
    __shared__ __align__(16) __half Abuf[2][128 * P2];
    __shared__ __align__(16) __half Bbuf[2][128 * P2];
    int tid = threadIdx.x, lane = tid & 31, w = tid >> 5;
    int wm = w >> 2, wn = w & 3;
    int tile = blockIdx.x, b = blockIdx.y;
    int p0 = tile * 128;
    const uint32_t* w32 = (const uint32_t*)d_w2s;
    float acc[4][4][4];
    #pragma unroll
    for (int mi = 0; mi < 4; mi++)
        #pragma unroll
        for (int ni = 0; ni < 4; ni++)
            #pragma unroll
            for (int q = 0; q < 4; q++) acc[mi][ni][q] = 0.f;

    // per-thread load slices: A = 8 uint32 (rows tid>>4 step 16? no: idx = tid + k*256)
    // A tile: 2048 uint32 -> 8 per thread; B tile: 512 uint4 -> 2 per thread.
    uint32_t ra[8];
    uint4 rb[2];

    auto ldg_tile = [&](int it, uint32_t* ra_, uint4* rb_) {
        int shift = it >> 2;
        int c0 = (it & 3) * 32;
        int r = shift / 3 - 1, s = shift % 3 - 1;
        #pragma unroll
        for (int k = 0; k < 8; k++) {
            int idx = tid + k * 256;
            int row = idx >> 4, cp = idx & 15;
            ra_[k] = w32[shift * 8192 + row * 64 + (c0 >> 1) + cp];
        }
        #pragma unroll
        for (int k = 0; k < 2; k++) {
            int idx = tid + k * 256;
            int p = idx >> 2, q = idx & 3;
            int pix = p0 + p;
            int ii = (pix >> 6) + r;
            int jj = (pix & 63) + s;
            uint4 v = make_uint4(0u, 0u, 0u, 0u);
            if ((unsigned)ii < 64u && (unsigned)jj < 64u)
                v = *(const uint4*)(d_hh + ((size_t)b * 4096 + ii * 64 + jj) * 128 + c0 + q * 8);
            rb_[k] = v;
        }
    };
    auto sts_tile = [&](int buf, const uint32_t* ra_, const uint4* rb_) {
        #pragma unroll
        for (int k = 0; k < 8; k++) {
            int idx = tid + k * 256;
            int row = idx >> 4, cp = idx & 15;
            *(uint32_t*)&Abuf[buf][row * P2 + cp * 2] = ra_[k];
        }
        #pragma unroll
        for (int k = 0; k < 2; k++) {
            int idx = tid + k * 256;
            int p = idx >> 2, q = idx & 3;
            *(uint4*)&Bbuf[buf][p * P2 + q * 8] = rb_[k];
        }
    };

    ldg_tile(0, ra, rb);
    sts_tile(0, ra, rb);
    __syncthreads();

    for (int it = 0; it < 36; it++) {
        int cur = it & 1;
        bool have = (it + 1) < 36;
        if (have) ldg_tile(it + 1, ra, rb);

        uint32_t smA = smem_to_u32(&Abuf[cur][0]);
        uint32_t smB = smem_to_u32(&Bbuf[cur][0]);
        #pragma unroll
        for (int ks = 0; ks < 2; ks++) {
            uint32_t a[4][4], bf[4][2];
            #pragma unroll
            for (int mi = 0; mi < 4; mi++) {
                uint32_t ad = smA + ((wm * 64 + mi * 16 + (lane & 15)) * P2 + ks * 16 + (lane >> 4) * 8) * 2;
                LDSM_X4(a[mi][0], a[mi][1], a[mi][2], a[mi][3], ad);
            }
            #pragma unroll
            for (int ni = 0; ni < 4; ni++) {
                uint32_t ad = smB + ((wn * 32 + ni * 8 + (lane & 7)) * P2 + ks * 16 + ((lane >> 3) & 1) * 8) * 2;
                LDSM_X2(bf[ni][0], bf[ni][1], ad);
            }
            #pragma unroll
            for (int mi = 0; mi < 4; mi++)
                #pragma unroll
                for (int ni = 0; ni < 4; ni++) mma16816(acc[mi][ni], a[mi], bf[ni]);
        }

        if (have) sts_tile(1 - cur, ra, rb);
        __syncthreads();
    }

    int mrow = lane >> 2, ncol = (lane & 3) * 2;
    #pragma unroll
    for (int mi = 0; mi < 4; mi++) {
        int o = wm * 64 + mi * 16 + mrow;
        float bb0 = b2[o], bb1 = b2[o + 8];
        #pragma unroll
        for (int ni = 0; ni < 4; ni++) {
            int p = p0 + wn * 32 + ni * 8 + ncol;
            float* dst = out + (size_t)(b * NC + o) * 4096 + p;
            *(float2*)dst = make_float2(leaky(acc[mi][ni][0] + bb0), leaky(acc[mi][ni][1] + bb0));
            *(float2*)(dst + (size_t)8 * 4096) = make_float2(leaky(acc[mi][ni][2] + bb1), leaky(acc[mi][ni][3] + bb1));
        }
    }
}

// ---------------- scores + g ----------------
__global__ void k_scoresg(const float* __restrict__ men2rel, const float* __restrict__ score_w,
                          const int* __restrict__ edge_mat, const float* __restrict__ m_bias) {
    int i = blockIdx.x, b = blockIdx.y, j = threadIdx.x;
    __shared__ float sw[128];
    sw[j] = score_w[j]; sw[j + 64] = score_w[j + 64];
    __syncthreads();
    float s = 0.f;
    #pragma unroll 8
    for (int c = 0; c < NC; c++) s += sw[c] * men2rel[((b * NC + c) * 64 + i) * 64 + j];
    int idx = (b * NE + i) * NE + j;
    float Lv = leaky(d_xs[b * 64 + j] + d_yo[b * 64 + i]);
    d_g[idx] = Lv + leaky(s) + d_eltype[edge_mat[idx]] + m_bias[idx];
}

// ---------------- final softmax + output GEMMs ----------------
__global__ __launch_bounds__(256) void k_final(const float* __restrict__ x, const float* __restrict__ y,
                                               float* __restrict__ out) {
    __shared__ float G[64 * 65];
    __shared__ float lin[64 * 65];
    int ihalf = blockIdx.x, b = blockIdx.y, z = blockIdx.z;
    int t = threadIdx.x;
    int i0b = ihalf * 64;
    const float* linsrc = z ? d_xlin : d_ylin;
    for (int idx = t; idx < 4096; idx += 256) {
        int n = idx >> 6, iL = idx & 63;
        lin[n * 65 + iL] = linsrc[(b * NE + n) * NCIN + i0b + iL];
    }
    if (t < 64) {
        int row = t;
        const float* gb = d_g + b * 4096;
        float mx = -1e30f;
        for (int k = 0; k < 64; k++) {
            float gv = z ? gb[k * 64 + row] : gb[row * 64 + k];
            G[row * 65 + k] = gv;
            mx = fmaxf(mx, gv);
        }
        float s = 0.f;
        for (int k = 0; k < 64; k++) { float ev = __expf(G[row * 65 + k] - mx); G[row * 65 + k] = ev; s += ev; }
        float inv = 1.f / s;
        for (int k = 0; k < 64; k++) G[row * 65 + k] *= inv;
    }
    __syncthreads();

    int ig = t >> 4, mg = t & 15;
    int iL0 = ig * 4, m0 = mg * 4;
    float acc[4][4];
    #pragma unroll
    for (int u = 0; u < 4; u++)
        #pragma unroll
        for (int v = 0; v < 4; v++) acc[u][v] = 0.f;
    for (int k = 0; k < 64; k++) {
        float av[4], bv[4];
        #pragma unroll
        for (int u = 0; u < 4; u++) av[u] = lin[k * 65 + iL0 + u];
        #pragma unroll
        for (int v = 0; v < 4; v++) bv[v] = G[(m0 + v) * 65 + k];
        #pragma unroll
        for (int u = 0; u < 4; u++)
            #pragma unroll
            for (int v = 0; v < 4; v++) acc[u][v] += av[u] * bv[v];
    }
    const float* resid = z ? y : x;
    float* outb = out + (z ? NB * NCIN * NE : 0);
    #pragma unroll
    for (int u = 0; u < 4; u++) {
        int i = i0b + iL0 + u;
        #pragma unroll
        for (int v = 0; v < 4; v++) {
            int m = m0 + v;
            outb[(b * NCIN + i) * NE + m] = acc[u][v] + resid[b * NCIN * NE + i * NE + m];
        }
    }
}

extern "C" void kernel_launch(void* const* d_in, const int* in_sizes, int n_in,
                              void* d_out, int out_size) {
    const float* x          = (const float*)d_in[0];
    const float* y          = (const float*)d_in[1];
    const float* m_bias     = (const float*)d_in[2];
    const int*   edge_mat   = (const int*)d_in[3];
    const float* p_bias     = (const float*)d_in[4];
    const int*   path_mat   = (const int*)d_in[5];
    const float* pre_out    = (const float*)d_in[6];
    const float* xc1_w      = (const float*)d_in[7];
    const float* yc1_w      = (const float*)d_in[8];
    const float* xc2_w      = (const float*)d_in[9];
    const float* xc2_b      = (const float*)d_in[10];
    const float* yc2_w      = (const float*)d_in[11];
    const float* yc2_b      = (const float*)d_in[12];
    const float* pconv_w    = (const float*)d_in[13];
    const float* econv_w    = (const float*)d_in[14];
    const float* conv1_w    = (const float*)d_in[15];
    const float* conv1_b    = (const float*)d_in[16];
    const float* conv2_w    = (const float*)d_in[17];
    const float* conv2_b    = (const float*)d_in[18];
    const float* score_w    = (const float*)d_in[19];
    const float* xlin_w     = (const float*)d_in[20];
    const float* ylin_w     = (const float*)d_in[21];
    const float* edge_table = (const float*)d_in[22];
    const float* path_table = (const float*)d_in[23];

    float* out = (float*)d_out;
    float* out_men2rel = out + 2 * NB * NCIN * NE;

    k_front<<<817, 256>>>(conv1_w, conv2_w, path_table, pconv_w, edge_table, econv_w,
                          xc1_w, yc1_w, xc2_w, yc2_w, xc2_b, yc2_b, x, y, xlin_w, ylin_w);
    { dim3 g(NE, NB); k_attn<<<g, 256>>>(path_mat, p_bias); }
    { dim3 g(32, NB); k_conv1_mma<<<g, 256>>>(pre_out, conv1_b); }
    { dim3 g(32, NB); k_conv2_mma<<<g, 256>>>(conv2_b, out_men2rel); }
    { dim3 g(64, NB); k_scoresg<<<g, 64>>>(out_men2rel, score_w, edge_mat, m_bias); }
    { dim3 g(2, NB, 2); k_final<<<g, 256>>>(x, y, out); }
}

// round 16
// speedup vs baseline: 1.4665x; 1.0215x over previous
#include <cuda_runtime.h>
#include <cuda_fp16.h>
#include <cstdint>

constexpr int NB = 8, NE = 64, NCIN = 128, NC = 128;

__device__ __forceinline__ float leaky(float v) { return v >= 0.f ? v : 0.1f * v; }

// ---------------- scratch (static device globals) ----------------
__device__ float  d_xf[NB * NC * NE];
__device__ float  d_yf[NB * NC * NE];
__device__ float  d_xs[NB * NE];
__device__ float  d_yo[NB * NE];
__device__ float  d_pltype[20];
__device__ float  d_eltype[10];
__device__ float  d_g[NB * NE * NE];
__device__ float  d_xlin[NB * NE * NCIN];
__device__ float  d_ylin[NB * NE * NCIN];
__device__ __half d_menh[NB * 4096 * 256];   // path_fea [b][pix][c]
__device__ __half d_hh[NB * 4096 * NC];      // conv1 out [b][pix][c]
__device__ __half d_w1h[NC * 384];
__device__ __half d_w2s[9 * NC * NC];

__device__ __forceinline__ uint32_t smem_to_u32(const void* p) {
    uint32_t a;
    asm("{ .reg .u64 t; cvta.to.shared.u64 t, %1; cvt.u32.u64 %0, t; }" : "=r"(a) : "l"(p));
    return a;
}
#define LDSM_X4(r0, r1, r2, r3, addr) \
    asm volatile("ldmatrix.sync.aligned.m8n8.x4.shared.b16 {%0,%1,%2,%3}, [%4];" \
        : "=r"(r0), "=r"(r1), "=r"(r2), "=r"(r3) : "r"(addr))
#define LDSM_X2(r0, r1, addr) \
    asm volatile("ldmatrix.sync.aligned.m8n8.x2.shared.b16 {%0,%1}, [%2];" \
        : "=r"(r0), "=r"(r1) : "r"(addr))
__device__ __forceinline__ void mma16816(float* c, const uint32_t* a, const uint32_t* b) {
    asm volatile("mma.sync.aligned.m16n8k16.row.col.f32.f16.f16.f32 "
                 "{%0,%1,%2,%3}, {%4,%5,%6,%7}, {%8,%9}, {%0,%1,%2,%3};"
                 : "+f"(c[0]), "+f"(c[1]), "+f"(c[2]), "+f"(c[3])
                 : "r"(a[0]), "r"(a[1]), "r"(a[2]), "r"(a[3]), "r"(b[0]), "r"(b[1]));
}
constexpr int PITCH = 72;
constexpr int TPITCH = 136;
constexpr int P2 = 40;   // pipelined tile pitch (80B rows; ldmatrix conflict-free)

// ---------------- merged front (R14/R15 proven) ----------------
__global__ __launch_bounds__(256) void k_front(
        const float* __restrict__ w1, const float* __restrict__ w2,
        const float* __restrict__ path_table, const float* __restrict__ pconv_w,
        const float* __restrict__ edge_table, const float* __restrict__ econv_w,
        const float* __restrict__ xc1_w, const float* __restrict__ yc1_w,
        const float* __restrict__ xc2_w, const float* __restrict__ yc2_w,
        const float* __restrict__ xc2_b, const float* __restrict__ yc2_b,
        const float* __restrict__ x, const float* __restrict__ y,
        const float* __restrict__ xlw, const float* __restrict__ ylw) {
    __shared__ __align__(16) char fbuf[33024];
    int blk = blockIdx.x, tid = threadIdx.x;

    if (blk < 192) {
        int i = blk * 256 + tid;
        d_w1h[i] = __float2half(w1[i]);
        return;
    }
    if (blk < 768) {
        int i = (blk - 192) * 256 + tid;
        int shift = i / 16384, rem = i % 16384;
        int o = rem >> 7, c = rem & 127;
        d_w2s[i] = __float2half(w2[(o * NC + c) * 9 + shift]);
        return;
    }
    if (blk == 768) {
        float* swx = (float*)fbuf;
        float* swy = (float*)fbuf + 128;
        if (tid < 20) {
            float s = 0.f;
            #pragma unroll
            for (int d = 0; d < 32; d++) s += path_table[tid * 32 + d] * pconv_w[d];
            d_pltype[tid] = leaky(s);
        }
        if (tid < 10) {
            float s = 0.f;
            #pragma unroll
            for (int d = 0; d < 32; d++) s += edge_table[tid * 32 + d] * econv_w[d];
            d_eltype[tid] = leaky(s);
        }
        if (tid < 128) {
            float ax = 0.f, ay = 0.f;
            #pragma unroll 8
            for (int c = 0; c < NC; c++) {
                ax += xc2_w[c] * xc1_w[c * NCIN + tid];
                ay += yc2_w[c] * yc1_w[c * NCIN + tid];
            }
            swx[tid] = ax; swy[tid] = ay;
        }
        __syncthreads();
        for (int task = tid; task < 1024; task += 256) {
            int b = task >> 7, u = task & 127;
            if (u < 64) {
                const float* xb = x + b * NCIN * NE + u;
                float a0 = 0.f, a1 = 0.f;
                #pragma unroll 8
                for (int i = 0; i < NCIN; i += 2) { a0 += swx[i] * xb[i * NE]; a1 += swx[i + 1] * xb[(i + 1) * NE]; }
                d_xs[b * 64 + u] = a0 + a1 + xc2_b[0];
            } else {
                int m = u - 64;
                const float* yb = y + b * NCIN * NE + m;
                float a0 = 0.f, a1 = 0.f;
                #pragma unroll 8
                for (int i = 0; i < NCIN; i += 2) { a0 += swy[i] * yb[i * NE]; a1 += swy[i + 1] * yb[(i + 1) * NE]; }
                d_yo[b * 64 + m] = a0 + a1 + yc2_b[0];
            }
        }
        return;
    }
    if (blk < 785) {                               // xfyf: 16 blocks
        int bi = blk - 769;
        int b = bi >> 1, z = bi & 1;
        __half* As = (__half*)fbuf;
        __half* Bs = (__half*)(fbuf + 18432);
        const float* wsel = z ? yc1_w : xc1_w;
        const float* in = (z ? y : x) + b * NCIN * NE;
        float* outp     = (z ? d_yf : d_xf) + b * NC * NE;
        int lane = tid & 31, wp = tid >> 5;
        int wm = wp >> 1, wn = wp & 1;
        uint32_t smA = smem_to_u32(As), smB = smem_to_u32(Bs);
        float acc[2][4][4];
        #pragma unroll
        for (int mi = 0; mi < 2; mi++)
            #pragma unroll
            for (int ni = 0; ni < 4; ni++)
                #pragma unroll
                for (int q = 0; q < 4; q++) acc[mi][ni][q] = 0.f;
        for (int k0 = 0; k0 < 128; k0 += 64) {
            __syncthreads();
            for (int idx = tid; idx < 4096; idx += 256) {
                int c = idx >> 5, i2 = idx & 31;
                float2 f = *(const float2*)(wsel + c * 128 + k0 + i2 * 2);
                *(__half2*)&As[c * PITCH + i2 * 2] = __floats2half2_rn(f.x, f.y);
            }
            for (int idx = tid; idx < 2048; idx += 256) {
                int i = idx >> 5, m2 = idx & 31;
                float2 f = *(const float2*)(in + (k0 + i) * 64 + m2 * 2);
                Bs[(m2 * 2) * PITCH + i]     = __float2half(f.x);
                Bs[(m2 * 2 + 1) * PITCH + i] = __float2half(f.y);
            }
            __syncthreads();
            #pragma unroll
            for (int ks = 0; ks < 4; ks++) {
                uint32_t a[2][4], bf[4][2];
                #pragma unroll
                for (int mi = 0; mi < 2; mi++) {
                    uint32_t ad = smA + ((wm * 32 + mi * 16 + (lane & 15)) * PITCH + ks * 16 + (lane >> 4) * 8) * 2;
                    LDSM_X4(a[mi][0], a[mi][1], a[mi][2], a[mi][3], ad);
                }
                #pragma unroll
                for (int ni = 0; ni < 4; ni++) {
                    uint32_t ad = smB + ((wn * 32 + ni * 8 + (lane & 7)) * PITCH + ks * 16 + ((lane >> 3) & 1) * 8) * 2;
                    LDSM_X2(bf[ni][0], bf[ni][1], ad);
                }
                #pragma unroll
                for (int mi = 0; mi < 2; mi++)
                    #pragma unroll
                    for (int ni = 0; ni < 4; ni++) mma16816(acc[mi][ni], a[mi], bf[ni]);
            }
        }
        #pragma unroll
        for (int mi = 0; mi < 2; mi++) {
            int c = wm * 32 + mi * 16 + (lane >> 2);
            #pragma unroll
            for (int ni = 0; ni < 4; ni++) {
                int m = wn * 32 + ni * 8 + (lane & 3) * 2;
                *(float2*)(outp + c * 64 + m)       = make_float2(acc[mi][ni][0], acc[mi][ni][1]);
                *(float2*)(outp + (c + 8) * 64 + m) = make_float2(acc[mi][ni][2], acc[mi][ni][3]);
            }
        }
        return;
    }
    {                                              // lin: 32 blocks
        int li = blk - 785;
        int ihalf = li & 1, b = (li >> 1) & 7, z = li >> 4;
        float* wsm = (float*)fbuf;
        const float* w  = z ? ylw : xlw;
        const float* in = z ? y : x;
        float* outp     = z ? d_ylin : d_xlin;
        int i0b = ihalf * 64;
        for (int idx = tid; idx < 64 * 128; idx += 256) {
            int ii = idx >> 7, j = idx & 127;
            wsm[ii * 129 + j] = w[(i0b + ii) * NCIN + j];
        }
        __syncthreads();
        int ig = tid >> 4, mg = tid & 15;
        int iL0 = ig * 4, m0 = mg * 4;
        float acc[4][4];
        #pragma unroll
        for (int u = 0; u < 4; u++)
            #pragma unroll
            for (int v = 0; v < 4; v++) acc[u][v] = 0.f;
        const float* inb = in + b * NCIN * NE;
        for (int j = 0; j < 128; j++) {
            float av[4], bv[4];
            #pragma unroll
            for (int u = 0; u < 4; u++) av[u] = wsm[(iL0 + u) * 129 + j];
            #pragma unroll
            for (int v = 0; v < 4; v++) bv[v] = inb[j * NE + m0 + v];
            #pragma unroll
            for (int u = 0; u < 4; u++)
                #pragma unroll
                for (int v = 0; v < 4; v++) acc[u][v] += av[u] * bv[v];
        }
        #pragma unroll
        for (int u = 0; u < 4; u++)
            #pragma unroll
            for (int v = 0; v < 4; v++)
                outp[(b * NE + m0 + v) * NCIN + i0b + iL0 + u] = acc[u][v];
    }
}

// ---------------- per-(b,e) path attention (R13+ proven) ----------------
__global__ __launch_bounds__(256) void k_attn(const int* __restrict__ path_mat,
                                              const float* __restrict__ p_bias) {
    __shared__ __align__(16) float  loc[64 * 64];
    __shared__ __align__(16) __half Ah[64 * 64];
    __shared__ __align__(16) __half Fh[64 * TPITCH];
    __shared__ float rmax[64], rinv[64], cmax[64], cinv[64];
    __shared__ float sxs[64], syo[64], spl[20];
    int e = blockIdx.x, b = blockIdx.y, t = threadIdx.x;
    int lane = t & 31, w = t >> 5;
    const int*   pm = path_mat + (b * NE + e) * 4096;
    const float* pb = p_bias  + (size_t)(b * NE + e) * 4096;
    const float* xfb = d_xf + b * NC * NE;
    const float* yfb = d_yf + b * NC * NE;
    uint32_t AhB = smem_to_u32(Ah), FhB = smem_to_u32(Fh);
    __half* menb = d_menh + ((size_t)b * 4096 + e * 64) * 256;

    if (t < 20) spl[t] = d_pltype[t];
    else if (t >= 32 && t < 96)  sxs[t - 32] = d_xs[b * 64 + t - 32];
    else if (t >= 96 && t < 160) syo[t - 96] = d_yo[b * 64 + t - 96];
    __syncthreads();

    for (int idx = t; idx < 4096; idx += 256) {
        int m = idx >> 6, n = idx & 63;
        loc[idx] = leaky(sxs[n] + syo[m]) + spl[pm[idx]] + pb[idx];
    }
    for (int idx = t; idx < 4096; idx += 256) {
        int c = idx >> 5, n2 = idx & 31;
        float2 f = *(const float2*)(yfb + c * 64 + n2 * 2);
        uint32_t off = c * 128 + ((n2 * 4) ^ ((c & 7) * 16));
        *(__half2*)((char*)Fh + off) = __floats2half2_rn(f.x, f.y);
    }
    __syncthreads();

    {
        int row = w * 8;
        #pragma unroll
        for (int rr = 0; rr < 8; rr++) {
            float v0 = loc[(row + rr) * 64 + lane];
            float v1 = loc[(row + rr) * 64 + 32 + lane];
            float mx = fmaxf(v0, v1);
            #pragma unroll
            for (int o = 16; o > 0; o >>= 1) mx = fmaxf(mx, __shfl_xor_sync(0xffffffff, mx, o));
            float s = __expf(v0 - mx) + __expf(v1 - mx);
            #pragma unroll
            for (int o = 16; o > 0; o >>= 1) s += __shfl_xor_sync(0xffffffff, s, o);
            if (lane == 0) { rmax[row + rr] = mx; rinv[row + rr] = 1.f / s; }
        }
    }
    if (t < 64) {
        float mx = -1e30f;
        for (int m = 0; m < 64; m++) mx = fmaxf(mx, loc[m * 64 + t]);
        float s = 0.f;
        for (int m = 0; m < 64; m++) s += __expf(loc[m * 64 + t] - mx);
        cmax[t] = mx; cinv[t] = 1.f / s;
    }
    __syncthreads();

    for (int idx = t; idx < 2048; idx += 256) {
        int m = idx >> 5, n2 = idx & 31;
        float v0 = __expf(loc[m * 64 + n2 * 2]     - rmax[m]) * rinv[m];
        float v1 = __expf(loc[m * 64 + n2 * 2 + 1] - rmax[m]) * rinv[m];
        uint32_t off = m * 128 + ((n2 * 4) ^ ((m & 7) * 16));
        *(__half2*)((char*)Ah + off) = __floats2half2_rn(v0, v1);
    }
    __syncthreads();

    float acc[8][4];
    #pragma unroll
    for (int ni = 0; ni < 8; ni++)
        #pragma unroll
        for (int q = 0; q < 4; q++) acc[ni][q] = 0.f;
    #pragma unroll
    for (int ks = 0; ks < 4; ks++) {
        uint32_t a[4];
        int row = w * 16 + (lane & 15);
        uint32_t off = row * 128 + (((ks * 16 + (lane >> 4) * 8) * 2) ^ ((row & 7) * 16));
        LDSM_X4(a[0], a[1], a[2], a[3], FhB + off);
        #pragma unroll
        for (int ni = 0; ni < 8; ni++) {
            int mr = ni * 8 + (lane & 7);
            uint32_t offb = mr * 128 + (((ks * 16 + ((lane >> 3) & 1) * 8) * 2) ^ ((mr & 7) * 16));
            uint32_t b0, b1;
            LDSM_X2(b0, b1, AhB + offb);
            uint32_t bf[2] = {b0, b1};
            mma16816(acc[ni], a, bf);
        }
    }
    __syncthreads();

    {
        int cr = w * 16 + (lane >> 2);
        #pragma unroll
        for (int ni = 0; ni < 8; ni++) {
            int mc = ni * 8 + (lane & 3) * 2;
            float2 r0 = *(const float2*)(xfb + cr * 64 + mc);
            float2 r1 = *(const float2*)(xfb + (cr + 8) * 64 + mc);
            Fh[mc * TPITCH + cr]           = __float2half(leaky(acc[ni][0] + r0.x));
            Fh[(mc + 1) * TPITCH + cr]     = __float2half(leaky(acc[ni][1] + r0.y));
            Fh[mc * TPITCH + cr + 8]       = __float2half(leaky(acc[ni][2] + r1.x));
            Fh[(mc + 1) * TPITCH + cr + 8] = __float2half(leaky(acc[ni][3] + r1.y));
        }
    }
    __syncthreads();
    for (int idx = t; idx < 1024; idx += 256) {
        int row = idx >> 4, q = idx & 15;
        *(uint4*)(menb + (size_t)row * 256 + q * 8) = *(uint4*)&Fh[row * TPITCH + q * 8];
    }
    __syncthreads();

    for (int idx = t; idx < 2048; idx += 256) {
        int n = idx & 63, m2 = idx >> 6;
        float v0 = __expf(loc[(m2 * 2) * 64 + n]     - cmax[n]) * cinv[n];
        float v1 = __expf(loc[(m2 * 2 + 1) * 64 + n] - cmax[n]) * cinv[n];
        uint32_t off = n * 128 + ((m2 * 4) ^ ((n & 7) * 16));
        *(__half2*)((char*)Ah + off) = __floats2half2_rn(v0, v1);
    }
    for (int idx = t; idx < 4096; idx += 256) {
        int c = idx >> 5, n2 = idx & 31;
        float2 f = *(const float2*)(xfb + c * 64 + n2 * 2);
        uint32_t off = c * 128 + ((n2 * 4) ^ ((c & 7) * 16));
        *(__half2*)((char*)Fh + off) = __floats2half2_rn(f.x, f.y);
    }
    __syncthreads();

    #pragma unroll
    for (int ni = 0; ni < 8; ni++)
        #pragma unroll
        for (int q = 0; q < 4; q++) acc[ni][q] = 0.f;
    #pragma unroll
    for (int ks = 0; ks < 4; ks++) {
        uint32_t a[4];
        int row = w * 16 + (lane & 15);
        uint32_t off = row * 128 + (((ks * 16 + (lane >> 4) * 8) * 2) ^ ((row & 7) * 16));
        LDSM_X4(a[0], a[1], a[2], a[3], FhB + off);
        #pragma unroll
        for (int ni = 0; ni < 8; ni++) {
            int nr = ni * 8 + (lane & 7);
            uint32_t offb = nr * 128 + (((ks * 16 + ((lane >> 3) & 1) * 8) * 2) ^ ((nr & 7) * 16));
            uint32_t b0, b1;
            LDSM_X2(b0, b1, AhB + offb);
            uint32_t bf[2] = {b0, b1};
            mma16816(acc[ni], a, bf);
        }
    }
    __syncthreads();

    {
        int cr = w * 16 + (lane >> 2);
        #pragma unroll
        for (int ni = 0; ni < 8; ni++) {
            int nc = ni * 8 + (lane & 3) * 2;
            float2 r0 = *(const float2*)(yfb + cr * 64 + nc);
            float2 r1 = *(const float2*)(yfb + (cr + 8) * 64 + nc);
            Fh[nc * TPITCH + cr]           = __float2half(leaky(acc[ni][0] + r0.x));
            Fh[(nc + 1) * TPITCH + cr]     = __float2half(leaky(acc[ni][1] + r0.y));
            Fh[nc * TPITCH + cr + 8]       = __float2half(leaky(acc[ni][2] + r1.x));
            Fh[(nc + 1) * TPITCH + cr + 8] = __float2half(leaky(acc[ni][3] + r1.y));
        }
    }
    __syncthreads();
    for (int idx = t; idx < 1024; idx += 256) {
        int row = idx >> 4, q = idx & 15;
        *(uint4*)(menb + (size_t)row * 256 + 128 + q * 8) = *(uint4*)&Fh[row * TPITCH + q * 8];
    }
}

// ---------------- conv1: register-staged double-buffered pipeline ----------------
__global__ __launch_bounds__(256) void k_conv1_mma(const float* __restrict__ pre_out,
                                                   const float* __restrict__ b1) {
    __shared__ __align__(16) char cbuf[4 * 128 * P2 * 2];   // 40960B; Ts aliases after loop
    __half (*Abuf)[128 * P2] = (__half (*)[128 * P2])cbuf;
    __half (*Bbuf)[128 * P2] = (__half (*)[128 * P2])(cbuf + 2 * 128 * P2 * 2);
    __half* Ts = (__half*)cbuf;   // 128*136 halfs = 34816B <= 40960B
    int tid = threadIdx.x, lane = tid & 31, w = tid >> 5;
    int wm = w >> 2, wn = w & 3;
    int tile = blockIdx.x, b = blockIdx.y;
    int p0 = tile * 128;
    const uint32_t* w32 = (const uint32_t*)d_w1h;
    float acc[4][4][4];
    #pragma unroll
    for (int mi = 0; mi < 4; mi++)
        #pragma unroll
        for (int ni = 0; ni < 4; ni++)
            #pragma unroll
            for (int q = 0; q < 4; q++) acc[mi][ni][q] = 0.f;

    uint32_t ra[8];
    uint4 rb[2];
    float2 rf[8];

    auto ldg1 = [&](int it) {
        int k0h = it * 16;   // uint32 offset within 192-wide row
        #pragma unroll
        for (int k = 0; k < 8; k++) {
            int idx = tid + k * 256;
            int row = idx >> 4, cp = idx & 15;
            ra[k] = w32[row * 192 + k0h + cp];
        }
        if (it < 8) {
            #pragma unroll
            for (int k = 0; k < 2; k++) {
                int idx = tid + k * 256;
                int p = idx >> 2, q = idx & 3;
                rb[k] = *(const uint4*)(d_menh + ((size_t)b * 4096 + p0 + p) * 256 + it * 32 + q * 8);
            }
        } else {
            #pragma unroll
            for (int k = 0; k < 8; k++) {
                int idx = tid + k * 256;
                int kk = idx >> 6, pp2 = idx & 63;
                rf[k] = *(const float2*)(pre_out + ((size_t)b * 128 + (it - 8) * 32 + kk) * 4096 + p0 + pp2 * 2);
            }
        }
    };
    auto sts1 = [&](int buf, int it) {
        #pragma unroll
        for (int k = 0; k < 8; k++) {
            int idx = tid + k * 256;
            int row = idx >> 4, cp = idx & 15;
            *(uint32_t*)&Abuf[buf][row * P2 + cp * 2] = ra[k];
        }
        if (it < 8) {
            #pragma unroll
            for (int k = 0; k < 2; k++) {
                int idx = tid + k * 256;
                int p = idx >> 2, q = idx & 3;
                *(uint4*)&Bbuf[buf][p * P2 + q * 8] = rb[k];
            }
        } else {
            #pragma unroll
            for (int k = 0; k < 8; k++) {
                int idx = tid + k * 256;
                int kk = idx >> 6, pp2 = idx & 63;
                Bbuf[buf][(pp2 * 2) * P2 + kk]     = __float2half(rf[k].x);
                Bbuf[buf][(pp2 * 2 + 1) * P2 + kk] = __float2half(rf[k].y);
            }
        }
    };

    ldg1(0);
    sts1(0, 0);
    __syncthreads();

    for (int it = 0; it < 12; it++) {
        int cur = it & 1;
        bool have = (it + 1) < 12;
        if (have) ldg1(it + 1);

        uint32_t smA = smem_to_u32(&Abuf[cur][0]);
        uint32_t smB = smem_to_u32(&Bbuf[cur][0]);
        #pragma unroll
        for (int ks = 0; ks < 2; ks++) {
            uint32_t a[4][4], bf[4][2];
            #pragma unroll
            for (int mi = 0; mi < 4; mi++) {
                uint32_t ad = smA + ((wm * 64 + mi * 16 + (lane & 15)) * P2 + ks * 16 + (lane >> 4) * 8) * 2;
                LDSM_X4(a[mi][0], a[mi][1], a[mi][2], a[mi][3], ad);
            }
            #pragma unroll
            for (int ni = 0; ni < 4; ni += 2) {
                int rowsel = wn * 32 + (ni + ((lane >> 4) & 1)) * 8 + (lane & 7);
                uint32_t ad = smB + (rowsel * P2 + ks * 16 + ((lane >> 3) & 1) * 8) * 2;
                LDSM_X4(bf[ni][0], bf[ni][1], bf[ni + 1][0], bf[ni + 1][1], ad);
            }
            #pragma unroll
            for (int mi = 0; mi < 4; mi++)
                #pragma unroll
                for (int ni = 0; ni < 4; ni++) mma16816(acc[mi][ni], a[mi], bf[ni]);
        }

        if (have) sts1(1 - cur, it + 1);
        __syncthreads();
    }

    int mrow = lane >> 2, ncol = (lane & 3) * 2;
    #pragma unroll
    for (int mi = 0; mi < 4; mi++) {
        int o = wm * 64 + mi * 16 + mrow;
        float bb0 = b1[o], bb1 = b1[o + 8];
        #pragma unroll
        for (int ni = 0; ni < 4; ni++) {
            int p = wn * 32 + ni * 8 + ncol;
            Ts[p * TPITCH + o]           = __float2half(leaky(acc[mi][ni][0] + bb0));
            Ts[(p + 1) * TPITCH + o]     = __float2half(leaky(acc[mi][ni][1] + bb0));
            Ts[p * TPITCH + o + 8]       = __float2half(leaky(acc[mi][ni][2] + bb1));
            Ts[(p + 1) * TPITCH + o + 8] = __float2half(leaky(acc[mi][ni][3] + bb1));
        }
    }
    __syncthreads();
    for (int idx = tid; idx < 2048; idx += 256) {
        int row = idx >> 4, q = idx & 15;
        *(uint4*)(d_hh + ((size_t)b * 4096 + p0 + row) * 128 + q * 8) = *(uint4*)&Ts[row * TPITCH + q * 8];
    }
}

// ---------------- conv2 3x3: pipelined (R15) + B ldmatrix x4 ----------------
__global__ __launch_bounds__(256) void k_conv2_mma(const float* __restrict__ b2,
                                                   float* __restrict__ out) {
    __shared__ __align__(16) __half Abuf[2][128 * P2];
    __shared__ __align__(16) __half Bbuf[2][128 * P2];
    int tid = threadIdx.x, lane = tid & 31, w = tid >> 5;
    int wm = w >> 2, wn = w & 3;
    int tile = blockIdx.x, b = blockIdx.y;
    int p0 = tile * 128;
    const uint32_t* w32 = (const uint32_t*)d_w2s;
    float acc[4][4][4];
    #pragma unroll
    for (int mi = 0; mi < 4; mi++)
        #pragma unroll
        for (int ni = 0; ni < 4; ni++)
            #pragma unroll
            for (int q = 0; q < 4; q++) acc[mi][ni][q] = 0.f;

    uint32_t ra[8];
    uint4 rb[2];

    auto ldg_tile = [&](int it, uint32_t* ra_, uint4* rb_) {
        int shift = it >> 2;
        int c0 = (it & 3) * 32;
        int r = shift / 3 - 1, s = shift % 3 - 1;
        #pragma unroll
        for (int k = 0; k < 8; k++) {
            int idx = tid + k * 256;
            int row = idx >> 4, cp = idx & 15;
            ra_[k] = w32[shift * 8192 + row * 64 + (c0 >> 1) + cp];
        }
        #pragma unroll
        for (int k = 0; k < 2; k++) {
            int idx = tid + k * 256;
            int p = idx >> 2, q = idx & 3;
            int pix = p0 + p;
            int ii = (pix >> 6) + r;
            int jj = (pix & 63) + s;
            uint4 v = make_uint4(0u, 0u, 0u, 0u);
            if ((unsigned)ii < 64u && (unsigned)jj < 64u)
                v = *(const uint4*)(d_hh + ((size_t)b * 4096 + ii * 64 + jj) * 128 + c0 + q * 8);
            rb_[k] = v;
        }
    };
    auto sts_tile = [&](int buf, const uint32_t* ra_, const uint4* rb_) {
        #pragma unroll
        for (int k = 0; k < 8; k++) {
            int idx = tid + k * 256;
            int row = idx >> 4, cp = idx & 15;
            *(uint32_t*)&Abuf[buf][row * P2 + cp * 2] = ra_[k];
        }
        #pragma unroll
        for (int k = 0; k < 2; k++) {
            int idx = tid + k * 256;
            int p = idx >> 2, q = idx & 3;
            *(uint4*)&Bbuf[buf][p * P2 + q * 8] = rb_[k];
        }
    };

    ldg_tile(0, ra, rb);
    sts_tile(0, ra, rb);
    __syncthreads();

    for (int it = 0; it < 36; it++) {
        int cur = it & 1;
        bool have = (it + 1) < 36;
        if (have) ldg_tile(it + 1, ra, rb);

        uint32_t smA = smem_to_u32(&Abuf[cur][0]);
        uint32_t smB = smem_to_u32(&Bbuf[cur][0]);
        #pragma unroll
        for (int ks = 0; ks < 2; ks++) {
            uint32_t a[4][4], bf[4][2];
            #pragma unroll
            for (int mi = 0; mi < 4; mi++) {
                uint32_t ad = smA + ((wm * 64 + mi * 16 + (lane & 15)) * P2 + ks * 16 + (lane >> 4) * 8) * 2;
                LDSM_X4(a[mi][0], a[mi][1], a[mi][2], a[mi][3], ad);
            }
            #pragma unroll
            for (int ni = 0; ni < 4; ni += 2) {
                int rowsel = wn * 32 + (ni + ((lane >> 4) & 1)) * 8 + (lane & 7);
                uint32_t ad = smB + (rowsel * P2 + ks * 16 + ((lane >> 3) & 1) * 8) * 2;
                LDSM_X4(bf[ni][0], bf[ni][1], bf[ni + 1][0], bf[ni + 1][1], ad);
            }
            #pragma unroll
            for (int mi = 0; mi < 4; mi++)
                #pragma unroll
                for (int ni = 0; ni < 4; ni++) mma16816(acc[mi][ni], a[mi], bf[ni]);
        }

        if (have) sts_tile(1 - cur, ra, rb);
        __syncthreads();
    }

    int mrow = lane >> 2, ncol = (lane & 3) * 2;
    #pragma unroll
    for (int mi = 0; mi < 4; mi++) {
        int o = wm * 64 + mi * 16 + mrow;
        float bb0 = b2[o], bb1 = b2[o + 8];
        #pragma unroll
        for (int ni = 0; ni < 4; ni++) {
            int p = p0 + wn * 32 + ni * 8 + ncol;
            float* dst = out + (size_t)(b * NC + o) * 4096 + p;
            *(float2*)dst = make_float2(leaky(acc[mi][ni][0] + bb0), leaky(acc[mi][ni][1] + bb0));
            *(float2*)(dst + (size_t)8 * 4096) = make_float2(leaky(acc[mi][ni][2] + bb1), leaky(acc[mi][ni][3] + bb1));
        }
    }
}

// ---------------- scores + g ----------------
__global__ void k_scoresg(const float* __restrict__ men2rel, const float* __restrict__ score_w,
                          const int* __restrict__ edge_mat, const float* __restrict__ m_bias) {
    int i = blockIdx.x, b = blockIdx.y, j = threadIdx.x;
    __shared__ float sw[128];
    sw[j] = score_w[j]; sw[j + 64] = score_w[j + 64];
    __syncthreads();
    float s = 0.f;
    #pragma unroll 8
    for (int c = 0; c < NC; c++) s += sw[c] * men2rel[((b * NC + c) * 64 + i) * 64 + j];
    int idx = (b * NE + i) * NE + j;
    float Lv = leaky(d_xs[b * 64 + j] + d_yo[b * 64 + i]);
    d_g[idx] = Lv + leaky(s) + d_eltype[edge_mat[idx]] + m_bias[idx];
}

// ---------------- final softmax + output GEMMs ----------------
__global__ __launch_bounds__(256) void k_final(const float* __restrict__ x, const float* __restrict__ y,
                                               float* __restrict__ out) {
    __shared__ float G[64 * 65];
    __shared__ float lin[64 * 65];
    int ihalf = blockIdx.x, b = blockIdx.y, z = blockIdx.z;
    int t = threadIdx.x;
    int i0b = ihalf * 64;
    const float* linsrc = z ? d_xlin : d_ylin;
    for (int idx = t; idx < 4096; idx += 256) {
        int n = idx >> 6, iL = idx & 63;
        lin[n * 65 + iL] = linsrc[(b * NE + n) * NCIN + i0b + iL];
    }
    if (t < 64) {
        int row = t;
        const float* gb = d_g + b * 4096;
        float mx = -1e30f;
        for (int k = 0; k < 64; k++) {
            float gv = z ? gb[k * 64 + row] : gb[row * 64 + k];
            G[row * 65 + k] = gv;
            mx = fmaxf(mx, gv);
        }
        float s = 0.f;
        for (int k = 0; k < 64; k++) { float ev = __expf(G[row * 65 + k] - mx); G[row * 65 + k] = ev; s += ev; }
        float inv = 1.f / s;
        for (int k = 0; k < 64; k++) G[row * 65 + k] *= inv;
    }
    __syncthreads();

    int ig = t >> 4, mg = t & 15;
    int iL0 = ig * 4, m0 = mg * 4;
    float acc[4][4];
    #pragma unroll
    for (int u = 0; u < 4; u++)
        #pragma unroll
        for (int v = 0; v < 4; v++) acc[u][v] = 0.f;
    for (int k = 0; k < 64; k++) {
        float av[4], bv[4];
        #pragma unroll
        for (int u = 0; u < 4; u++) av[u] = lin[k * 65 + iL0 + u];
        #pragma unroll
        for (int v = 0; v < 4; v++) bv[v] = G[(m0 + v) * 65 + k];
        #pragma unroll
        for (int u = 0; u < 4; u++)
            #pragma unroll
            for (int v = 0; v < 4; v++) acc[u][v] += av[u] * bv[v];
    }
    const float* resid = z ? y : x;
    float* outb = out + (z ? NB * NCIN * NE : 0);
    #pragma unroll
    for (int u = 0; u < 4; u++) {
        int i = i0b + iL0 + u;
        #pragma unroll
        for (int v = 0; v < 4; v++) {
            int m = m0 + v;
            outb[(b * NCIN + i) * NE + m] = acc[u][v] + resid[b * NCIN * NE + i * NE + m];
        }
    }
}

extern "C" void kernel_launch(void* const* d_in, const int* in_sizes, int n_in,
                              void* d_out, int out_size) {
    const float* x          = (const float*)d_in[0];
    const float* y          = (const float*)d_in[1];
    const float* m_bias     = (const float*)d_in[2];
    const int*   edge_mat   = (const int*)d_in[3];
    const float* p_bias     = (const float*)d_in[4];
    const int*   path_mat   = (const int*)d_in[5];
    const float* pre_out    = (const float*)d_in[6];
    const float* xc1_w      = (const float*)d_in[7];
    const float* yc1_w      = (const float*)d_in[8];
    const float* xc2_w      = (const float*)d_in[9];
    const float* xc2_b      = (const float*)d_in[10];
    const float* yc2_w      = (const float*)d_in[11];
    const float* yc2_b      = (const float*)d_in[12];
    const float* pconv_w    = (const float*)d_in[13];
    const float* econv_w    = (const float*)d_in[14];
    const float* conv1_w    = (const float*)d_in[15];
    const float* conv1_b    = (const float*)d_in[16];
    const float* conv2_w    = (const float*)d_in[17];
    const float* conv2_b    = (const float*)d_in[18];
    const float* score_w    = (const float*)d_in[19];
    const float* xlin_w     = (const float*)d_in[20];
    const float* ylin_w     = (const float*)d_in[21];
    const float* edge_table = (const float*)d_in[22];
    const float* path_table = (const float*)d_in[23];

    float* out = (float*)d_out;
    float* out_men2rel = out + 2 * NB * NCIN * NE;

    k_front<<<817, 256>>>(conv1_w, conv2_w, path_table, pconv_w, edge_table, econv_w,
                          xc1_w, yc1_w, xc2_w, yc2_w, xc2_b, yc2_b, x, y, xlin_w, ylin_w);
    { dim3 g(NE, NB); k_attn<<<g, 256>>>(path_mat, p_bias); }
    { dim3 g(32, NB); k_conv1_mma<<<g, 256>>>(pre_out, conv1_b); }
    { dim3 g(32, NB); k_conv2_mma<<<g, 256>>>(conv2_b, out_men2rel); }
    { dim3 g(64, NB); k_scoresg<<<g, 64>>>(out_men2rel, score_w, edge_mat, m_bias); }
    { dim3 g(2, NB, 2); k_final<<<g, 256>>>(x, y, out); }
}